// round 9
// baseline (speedup 1.0000x reference)
#include <cuda_runtime.h>
#include <math.h>

#define NN   8192
#define EE   131072
#define IND  3000
#define H1D  256
#define H2D  64
#define KSPL 1504   // k-split boundary: 1504 = 188*8, 3000-1504 = 1496 = 187*8

typedef unsigned long long u64;

// ---------------- scratch ----------------
__device__ float g_XWa  [NN*H1D];   // k-slice 0 partial
__device__ float g_XWb  [NN*H1D];   // k-slice 1 partial
__device__ float g_XW   [NN*H1D];   // summed
__device__ float g_H1   [NN*H1D];
__device__ float g_H1c  [NN*H1D];
__device__ float g_XW2  [NN*H2D];
__device__ float g_XW2c [NN*H2D];
__device__ float g_X2c  [NN*H2D];
__device__ float g_G1   [NN*H2D];
__device__ float g_G1c  [NN*H2D];
__device__ float g_dinv [NN];
__device__ int   g_deg  [NN];
__device__ int   g_off  [NN+1];
__device__ int   g_fill [NN];
__device__ int   g_permI[NN];
__device__ int   g_csr_src [EE];
__device__ int   g_csr_psrc[EE];
__device__ float g_csr_nm  [EE];
// zero at module load; only ever set to the same value for the same input.
__device__ int   g_notI64;

// ---------------- packed fp32x2 helpers ----------------
__device__ __forceinline__ u64 pack2(float x) {
    u64 r; asm("mov.b64 %0, {%1, %1};" : "=l"(r) : "f"(x)); return r;
}
__device__ __forceinline__ void fma2(u64& d, u64 a, u64 b) {
    asm("fma.rn.f32x2 %0, %1, %2, %0;" : "+l"(d) : "l"(a), "l"(b));
}

__device__ __forceinline__ int idx_at(const void* p, int i, int is64) {
    return is64 ? (int)((const long long*)p)[i] : ((const int*)p)[i];
}

// ---------------- setup: deg init + dtype detect in one pass --------
__global__ void k_init0det(const void* edges) {
    int i = blockIdx.x * blockDim.x + threadIdx.x;   // grid covers EE
    if (i < NN) g_deg[i] = 1;                        // self loop
    const long long* p = (const long long*)edges;
    long long v = p[i];
    if (v < 0 || v >= NN) g_notI64 = 1;
}

__global__ void k_perm_int(const void* permp) {
    int i = blockIdx.x * blockDim.x + threadIdx.x;
    if (i < NN) g_permI[i] = idx_at(permp, i, !g_notI64);
}

__global__ void k_deg_count(const void* edges) {
    int e = blockIdx.x * blockDim.x + threadIdx.x;
    if (e >= EE) return;
    atomicAdd(&g_deg[idx_at(edges, EE + e, !g_notI64)], 1);
}
__global__ void k_dinv() {
    int i = blockIdx.x * blockDim.x + threadIdx.x;
    if (i < NN) g_dinv[i] = rsqrtf((float)g_deg[i]);
}

// ---------------- CSR offsets: single-block scan --------------------
__global__ void k_scan() {
    __shared__ int partial[256];
    int t = threadIdx.x;
    int base = t * 32;
    int local[32];
    int sum = 0;
#pragma unroll
    for (int j = 0; j < 32; j++) {
        int c = g_deg[base + j] - 1;
        local[j] = sum;
        sum += c;
    }
    partial[t] = sum;
    __syncthreads();
    for (int o = 1; o < 256; o <<= 1) {
        int u = (t >= o) ? partial[t - o] : 0;
        __syncthreads();
        partial[t] += u;
        __syncthreads();
    }
    int off0 = partial[t] - sum;
#pragma unroll
    for (int j = 0; j < 32; j++) {
        int o = off0 + local[j];
        g_off[base + j]  = o;
        g_fill[base + j] = o;
    }
    if (t == 255) g_off[NN] = partial[255];
}

__global__ void k_fill(const void* edges) {
    int e = blockIdx.x * blockDim.x + threadIdx.x;
    if (e >= EE) return;
    int is64 = !g_notI64;
    int s = idx_at(edges, e, is64);
    int d = idx_at(edges, EE + e, is64);
    int pos = atomicAdd(&g_fill[d], 1);
    g_csr_src [pos] = s;
    g_csr_psrc[pos] = g_permI[s];
    g_csr_nm  [pos] = g_dinv[s] * g_dinv[d];
}

// ---------------- GEMM1: [8192,3000]@[3000,256], f32x2, K-split -----
// 64x128 tile, BK=8, 128 threads, 8x8 f32 microtile. blockIdx.z picks
// the K half -> 512 CTAs, ~4 CTAs/SM, doubled latency hiding.
__global__ void __launch_bounds__(128, 4)
k_gemm1(const float* __restrict__ A, const float* __restrict__ B) {
    __shared__ float As[2][8][64];
    __shared__ float Bs[2][8][128];
    int tid = threadIdx.x;
    int m0 = blockIdx.y * 64;
    int n0 = blockIdx.x * 128;
    int kb = blockIdx.z ? KSPL : 0;
    int klen = blockIdx.z ? (IND - KSPL) : KSPL;
    float* O = blockIdx.z ? g_XWb : g_XWa;

    int ty = tid >> 4, tx = tid & 15;
    int ar = tid >> 1, ak = (tid & 1) * 4;
    int br = tid >> 4, bc = (tid & 15) * 8;
    const float* Aptr = A + (size_t)(m0 + ar) * IND + kb + ak;
    const float* Bptr = B + (size_t)(kb + br) * H1D + n0 + bc;

    u64 acc[8][4];
#pragma unroll
    for (int i = 0; i < 8; i++)
#pragma unroll
        for (int j = 0; j < 4; j++) acc[i][j] = 0ull;

    float4 a0 = *(const float4*)Aptr;
    float4 b0 = *(const float4*)Bptr;
    float4 b1 = *(const float4*)(Bptr + 4);
    As[0][ak+0][ar] = a0.x; As[0][ak+1][ar] = a0.y;
    As[0][ak+2][ar] = a0.z; As[0][ak+3][ar] = a0.w;
    *(float4*)&Bs[0][br][bc]   = b0;
    *(float4*)&Bs[0][br][bc+4] = b1;
    __syncthreads();

    int buf = 0;
    for (int o = 8; o < klen; o += 8) {
        float4 an  = *(const float4*)(Aptr + o);
        float4 bn0 = *(const float4*)(Bptr + (size_t)o * H1D);
        float4 bn1 = *(const float4*)(Bptr + (size_t)o * H1D + 4);
#pragma unroll
        for (int kk = 0; kk < 8; kk++) {
            float ra[8];
            *(float4*)&ra[0] = *(const float4*)&As[buf][kk][ty*8];
            *(float4*)&ra[4] = *(const float4*)&As[buf][kk][ty*8+4];
            ulonglong2 rb01 = *(const ulonglong2*)&Bs[buf][kk][tx*8];
            ulonglong2 rb23 = *(const ulonglong2*)&Bs[buf][kk][tx*8+4];
#pragma unroll
            for (int i = 0; i < 8; i++) {
                u64 aa = pack2(ra[i]);
                fma2(acc[i][0], aa, rb01.x);
                fma2(acc[i][1], aa, rb01.y);
                fma2(acc[i][2], aa, rb23.x);
                fma2(acc[i][3], aa, rb23.y);
            }
        }
        buf ^= 1;
        As[buf][ak+0][ar] = an.x; As[buf][ak+1][ar] = an.y;
        As[buf][ak+2][ar] = an.z; As[buf][ak+3][ar] = an.w;
        *(float4*)&Bs[buf][br][bc]   = bn0;
        *(float4*)&Bs[buf][br][bc+4] = bn1;
        __syncthreads();
    }
#pragma unroll
    for (int kk = 0; kk < 8; kk++) {
        float ra[8];
        *(float4*)&ra[0] = *(const float4*)&As[buf][kk][ty*8];
        *(float4*)&ra[4] = *(const float4*)&As[buf][kk][ty*8+4];
        ulonglong2 rb01 = *(const ulonglong2*)&Bs[buf][kk][tx*8];
        ulonglong2 rb23 = *(const ulonglong2*)&Bs[buf][kk][tx*8+4];
#pragma unroll
        for (int i = 0; i < 8; i++) {
            u64 aa = pack2(ra[i]);
            fma2(acc[i][0], aa, rb01.x);
            fma2(acc[i][1], aa, rb01.y);
            fma2(acc[i][2], aa, rb23.x);
            fma2(acc[i][3], aa, rb23.y);
        }
    }

#pragma unroll
    for (int i = 0; i < 8; i++) {
        float* o = &O[(size_t)(m0 + ty*8 + i) * H1D + n0 + tx*8];
        ulonglong2 v01; v01.x = acc[i][0]; v01.y = acc[i][1];
        ulonglong2 v23; v23.x = acc[i][2]; v23.y = acc[i][3];
        *(ulonglong2*)o       = v01;
        *(ulonglong2*)(o + 4) = v23;
    }
}

// ---------------- reduce the two K-slices (deterministic) -----------
__global__ void k_reduceXW() {
    int i = blockIdx.x * blockDim.x + threadIdx.x;   // NN*H1D/4 threads
    float4 a = ((const float4*)g_XWa)[i];
    float4 b = ((const float4*)g_XWb)[i];
    ((float4*)g_XW)[i] = make_float4(a.x+b.x, a.y+b.y, a.z+b.z, a.w+b.w);
}

// ---------------- conv1 gather (float4, 2 rows/block) ---------------
__global__ void k_gather1(const float* __restrict__ b1) {
    int tid = threadIdx.x;            // 128
    int i = blockIdx.x * 2 + (tid >> 6);
    int l = (tid & 63) * 4;
    float s2 = g_dinv[i] * g_dinv[i];
    int pi = g_permI[i];
    float4 x0 = *(const float4*)&g_XW[(size_t)i  * H1D + l];
    float4 xp = *(const float4*)&g_XW[(size_t)pi * H1D + l];
    float4 acc  = make_float4(s2*x0.x, s2*x0.y, s2*x0.z, s2*x0.w);
    float4 accc = make_float4(s2*xp.x, s2*xp.y, s2*xp.z, s2*xp.w);
    int e1 = g_off[i + 1];
    for (int e = g_off[i]; e < e1; e++) {
        int s  = g_csr_src[e];
        int ps = g_csr_psrc[e];
        float nm = g_csr_nm[e];
        float4 xs = *(const float4*)&g_XW[(size_t)s  * H1D + l];
        float4 xq = *(const float4*)&g_XW[(size_t)ps * H1D + l];
        acc.x  += nm*xs.x; acc.y  += nm*xs.y; acc.z  += nm*xs.z; acc.w  += nm*xs.w;
        accc.x += nm*xq.x; accc.y += nm*xq.y; accc.z += nm*xq.z; accc.w += nm*xq.w;
    }
    float4 bb = *(const float4*)&b1[l];
    float4 v;
    v.x = fmaxf(acc.x + bb.x, 0.f); v.y = fmaxf(acc.y + bb.y, 0.f);
    v.z = fmaxf(acc.z + bb.z, 0.f); v.w = fmaxf(acc.w + bb.w, 0.f);
    *(float4*)&g_H1[(size_t)i * H1D + l] = v;
    v.x = fmaxf(accc.x + bb.x, 0.f); v.y = fmaxf(accc.y + bb.y, 0.f);
    v.z = fmaxf(accc.z + bb.z, 0.f); v.w = fmaxf(accc.w + bb.w, 0.f);
    *(float4*)&g_H1c[(size_t)i * H1D + l] = v;
}

// ---------------- GEMM2: [2*8192,256]@[256,64] ----------------------
__global__ void __launch_bounds__(256, 1)
k_gemm2(const float* __restrict__ W2) {
    const float* Am = (blockIdx.x < 64) ? g_H1  : g_H1c;
    float*       Om = (blockIdx.x < 64) ? g_XW2 : g_XW2c;
    int m0 = (blockIdx.x & 63) * 128;

    __shared__ float As[2][8][128];
    __shared__ float Bs[2][8][64];
    int tid = threadIdx.x;
    int ty = tid >> 4, tx = tid & 15;
    int ar = tid >> 1, ak = (tid & 1) * 4;
    int br = tid >> 5, bc = (tid & 31) * 2;
    const float* Aptr = Am + (size_t)(m0 + ar) * H1D + ak;
    const float* Bptr = W2 + (size_t)br * H2D + bc;

    u64 acc[8][2];
#pragma unroll
    for (int i = 0; i < 8; i++) { acc[i][0] = 0ull; acc[i][1] = 0ull; }

    float4 a0 = *(const float4*)Aptr;
    float2 b0 = *(const float2*)Bptr;
    As[0][ak+0][ar] = a0.x; As[0][ak+1][ar] = a0.y;
    As[0][ak+2][ar] = a0.z; As[0][ak+3][ar] = a0.w;
    *(float2*)&Bs[0][br][bc] = b0;
    __syncthreads();

    int buf = 0;
    for (int k0 = 8; k0 < H1D; k0 += 8) {
        float4 an = *(const float4*)(Aptr + k0);
        float2 bn = *(const float2*)(Bptr + (size_t)k0 * H2D);
#pragma unroll
        for (int kk = 0; kk < 8; kk++) {
            float ra[8];
            *(float4*)&ra[0] = *(const float4*)&As[buf][kk][ty*8];
            *(float4*)&ra[4] = *(const float4*)&As[buf][kk][ty*8+4];
            ulonglong2 rb = *(const ulonglong2*)&Bs[buf][kk][tx*4];
#pragma unroll
            for (int i = 0; i < 8; i++) {
                u64 aa = pack2(ra[i]);
                fma2(acc[i][0], aa, rb.x);
                fma2(acc[i][1], aa, rb.y);
            }
        }
        buf ^= 1;
        As[buf][ak+0][ar] = an.x; As[buf][ak+1][ar] = an.y;
        As[buf][ak+2][ar] = an.z; As[buf][ak+3][ar] = an.w;
        *(float2*)&Bs[buf][br][bc] = bn;
        __syncthreads();
    }
#pragma unroll
    for (int kk = 0; kk < 8; kk++) {
        float ra[8];
        *(float4*)&ra[0] = *(const float4*)&As[buf][kk][ty*8];
        *(float4*)&ra[4] = *(const float4*)&As[buf][kk][ty*8+4];
        ulonglong2 rb = *(const ulonglong2*)&Bs[buf][kk][tx*4];
#pragma unroll
        for (int i = 0; i < 8; i++) {
            u64 aa = pack2(ra[i]);
            fma2(acc[i][0], aa, rb.x);
            fma2(acc[i][1], aa, rb.y);
        }
    }

#pragma unroll
    for (int i = 0; i < 8; i++) {
        ulonglong2 v; v.x = acc[i][0]; v.y = acc[i][1];
        *(ulonglong2*)&Om[(size_t)(m0 + ty*8 + i) * H2D + tx*4] = v;
    }
}

// ---------------- conv2 gather (float4, 16 rows/block) --------------
__global__ void k_gather2(const float* __restrict__ b2, float* __restrict__ out_x1) {
    int t = threadIdx.x;            // 256
    int i = blockIdx.x * 16 + (t >> 4);
    int l = (t & 15) * 4;
    float s2 = g_dinv[i] * g_dinv[i];
    float4 x0 = *(const float4*)&g_XW2 [(size_t)i * H2D + l];
    float4 xc = *(const float4*)&g_XW2c[(size_t)i * H2D + l];
    float4 acc  = make_float4(s2*x0.x, s2*x0.y, s2*x0.z, s2*x0.w);
    float4 accc = make_float4(s2*xc.x, s2*xc.y, s2*xc.z, s2*xc.w);
    int e1 = g_off[i + 1];
    for (int e = g_off[i]; e < e1; e++) {
        int s = g_csr_src[e];
        float nm = g_csr_nm[e];
        float4 xs = *(const float4*)&g_XW2 [(size_t)s * H2D + l];
        float4 xq = *(const float4*)&g_XW2c[(size_t)s * H2D + l];
        acc.x  += nm*xs.x; acc.y  += nm*xs.y; acc.z  += nm*xs.z; acc.w  += nm*xs.w;
        accc.x += nm*xq.x; accc.y += nm*xq.y; accc.z += nm*xq.z; accc.w += nm*xq.w;
    }
    float4 bb = *(const float4*)&b2[l];
    float4 v;
    v.x = fmaxf(acc.x + bb.x, 0.f); v.y = fmaxf(acc.y + bb.y, 0.f);
    v.z = fmaxf(acc.z + bb.z, 0.f); v.w = fmaxf(acc.w + bb.w, 0.f);
    *(float4*)&out_x1[(size_t)i * H2D + l] = v;
    v.x = fmaxf(accc.x + bb.x, 0.f); v.y = fmaxf(accc.y + bb.y, 0.f);
    v.z = fmaxf(accc.z + bb.z, 0.f); v.w = fmaxf(accc.w + bb.w, 0.f);
    *(float4*)&g_X2c[(size_t)i * H2D + l] = v;
}

// ---------------- readout: compact nnz, then coalesced gather -------
__global__ void k_readout(const float* __restrict__ mask, const float* __restrict__ x1) {
    __shared__ int   s_idx[1024];
    __shared__ float s_val[1024];
    __shared__ int   s_cnt;
    __shared__ float s_rs;
    __shared__ float part1[4][H2D], part2[4][H2D];
    __shared__ float vs1[H2D], vs2[H2D];
    __shared__ float nrm1, nrm2;
    int i = blockIdx.x;
    int tid = threadIdx.x;  // 256
    if (tid == 0) { s_cnt = 0; s_rs = 0.f; }
    __syncthreads();

    float rs = 0.f;
    const float4* m4 = (const float4*)&mask[(size_t)i * NN];
    for (int j4 = tid; j4 < NN / 4; j4 += 256) {
        float4 m = m4[j4];
        rs += m.x + m.y + m.z + m.w;
        if (m.x != 0.f) { int p = atomicAdd(&s_cnt, 1); if (p < 1024) { s_idx[p] = j4*4;   s_val[p] = m.x; } }
        if (m.y != 0.f) { int p = atomicAdd(&s_cnt, 1); if (p < 1024) { s_idx[p] = j4*4+1; s_val[p] = m.y; } }
        if (m.z != 0.f) { int p = atomicAdd(&s_cnt, 1); if (p < 1024) { s_idx[p] = j4*4+2; s_val[p] = m.z; } }
        if (m.w != 0.f) { int p = atomicAdd(&s_cnt, 1); if (p < 1024) { s_idx[p] = j4*4+3; s_val[p] = m.w; } }
    }
#pragma unroll
    for (int o = 16; o; o >>= 1) rs += __shfl_down_sync(0xFFFFFFFFu, rs, o);
    if ((tid & 31) == 0) atomicAdd(&s_rs, rs);
    __syncthreads();

    int cnt = s_cnt < 1024 ? s_cnt : 1024;
    int g = tid >> 6, f = tid & 63;
    float a1 = 0.f, a2 = 0.f;
    for (int e = g; e < cnt; e += 4) {
        int j = s_idx[e];
        float mv = s_val[e];
        a1 += mv * x1   [(size_t)j * H2D + f];
        a2 += mv * g_X2c[(size_t)j * H2D + f];
    }
    part1[g][f] = a1;
    part2[g][f] = a2;
    __syncthreads();

    if (tid < H2D) {
        float inv = 1.0f / s_rs;
        vs1[tid] = (part1[0][tid] + part1[1][tid] + part1[2][tid] + part1[3][tid]) * inv;
        vs2[tid] = (part2[0][tid] + part2[1][tid] + part2[2][tid] + part2[3][tid]) * inv;
    }
    __syncthreads();
    if (tid == 0) {
        float s1 = 0.f, s2 = 0.f;
        for (int q = 0; q < H2D; q++) { s1 += vs1[q]*vs1[q]; s2 += vs2[q]*vs2[q]; }
        nrm1 = fmaxf(sqrtf(s1), 1e-12f);
        nrm2 = fmaxf(sqrtf(s2), 1e-12f);
    }
    __syncthreads();
    if (tid < H2D) {
        float v1 = vs1[tid] / nrm1;
        float v2 = vs2[tid] / nrm2;
        g_G1 [i*H2D + tid] = 1.0f / (1.0f + expf(-v1));
        g_G1c[i*H2D + tid] = 1.0f / (1.0f + expf(-v2));
    }
}

// ---------------- bilinear discriminator ----------------
__global__ void k_bilinear(const float* __restrict__ Wd, const float* __restrict__ bd,
                           const float* __restrict__ x1,
                           float* __restrict__ ret1, float* __restrict__ ret1c) {
    __shared__ float c1[H2D], c2[H2D], h[H2D], hc[H2D];
    __shared__ float red[4][H2D];
    int i = blockIdx.x;
    int k = threadIdx.x;  // 64
    c1[k] = g_G1 [i*H2D + k];
    c2[k] = g_G1c[i*H2D + k];
    h [k] = x1   [(size_t)i*H2D + k];
    hc[k] = g_X2c[(size_t)i*H2D + k];
    __syncthreads();
    float t1 = 0.f, t2 = 0.f;
    const float4* wr = (const float4*)&Wd[k * H2D];
#pragma unroll
    for (int j4 = 0; j4 < H2D / 4; j4++) {
        float4 w = wr[j4];
        t1 += w.x*c1[j4*4] + w.y*c1[j4*4+1] + w.z*c1[j4*4+2] + w.w*c1[j4*4+3];
        t2 += w.x*c2[j4*4] + w.y*c2[j4*4+1] + w.z*c2[j4*4+2] + w.w*c2[j4*4+3];
    }
    red[0][k] = h [k] * t1;
    red[1][k] = hc[k] * t1;
    red[2][k] = hc[k] * t2;
    red[3][k] = h [k] * t2;
    __syncthreads();
    if (k < 4) {
        float s = 0.f;
        for (int j = 0; j < H2D; j++) s += red[k][j];
        s += bd[0];
        if (k == 0) ret1 [i*2 + 0] = s;
        if (k == 1) ret1 [i*2 + 1] = s;
        if (k == 2) ret1c[i*2 + 0] = s;
        if (k == 3) ret1c[i*2 + 1] = s;
    }
}

// ---------------- launch ----------------
extern "C" void kernel_launch(void* const* d_in, const int* in_sizes, int n_in,
                              void* d_out, int out_size) {
    const float* gene = (const float*)d_in[0];
    const float* mask = (const float*)d_in[1];
    const float* W1   = (const float*)d_in[2];
    const float* b1   = (const float*)d_in[3];
    const float* W2   = (const float*)d_in[4];
    const float* b2   = (const float*)d_in[5];
    const float* Wd   = (const float*)d_in[6];
    const float* bd   = (const float*)d_in[7];
    const void*  edges = d_in[8];
    const void*  perm  = d_in[9];

    float* out    = (float*)d_out;
    float* out_x1 = out;
    float* out_r1 = out + NN * H2D;
    float* out_rc = out + NN * H2D + NN * 2;

    k_init0det <<<EE / 256, 256>>>(edges);
    k_perm_int <<<NN / 256, 256>>>(perm);
    k_deg_count<<<EE / 256, 256>>>(edges);

    dim3 gg1(H1D / 128, NN / 64, 2);   // (2, 128, 2) = 512 CTAs — launch #4
    k_gemm1    <<<gg1, 128>>>(gene, W1);
    k_reduceXW <<<NN * H1D / 4 / 256, 256>>>();

    k_dinv     <<<NN / 256, 256>>>();
    k_scan     <<<1, 256>>>();
    k_fill     <<<EE / 256, 256>>>(edges);

    k_gather1  <<<NN / 2, 128>>>(b1);
    k_gemm2    <<<128, 256>>>(W2);
    k_gather2  <<<NN / 16, 256>>>(b2, out_x1);

    k_readout  <<<NN, 256>>>(mask, out_x1);
    k_bilinear <<<NN, 64>>>(Wd, bd, out_x1, out_r1, out_rc);
}

// round 10
// speedup vs baseline: 1.0078x; 1.0078x over previous
#include <cuda_runtime.h>
#include <math.h>

#define NN   8192
#define EE   131072
#define IND  3000
#define H1D  256
#define H2D  64

typedef unsigned long long u64;

// ---------------- scratch ----------------
__device__ float g_XW   [NN*H1D];
__device__ float g_H1   [NN*H1D];
__device__ float g_H1c  [NN*H1D];
__device__ float g_XW2  [NN*H2D];
__device__ float g_XW2c [NN*H2D];
__device__ float g_X2c  [NN*H2D];
__device__ float g_G1   [NN*H2D];
__device__ float g_G1c  [NN*H2D];
__device__ float g_dinv [NN];
__device__ int   g_deg  [NN];
__device__ int   g_off  [NN+1];
__device__ int   g_fill [NN];
__device__ int   g_permI[NN];
__device__ int   g_csr_src [EE];
__device__ int   g_csr_psrc[EE];
__device__ float g_csr_nm  [EE];
// zero at module load; only ever set to the same value for the same input.
__device__ int   g_notI64;

// ---------------- packed fp32x2 helpers ----------------
__device__ __forceinline__ u64 pack2(float x) {
    u64 r; asm("mov.b64 %0, {%1, %1};" : "=l"(r) : "f"(x)); return r;
}
__device__ __forceinline__ void fma2(u64& d, u64 a, u64 b) {
    asm("fma.rn.f32x2 %0, %1, %2, %0;" : "+l"(d) : "l"(a), "l"(b));
}

__device__ __forceinline__ int idx_at(const void* p, int i, int is64) {
    return is64 ? (int)((const long long*)p)[i] : ((const int*)p)[i];
}

// ---------------- setup: deg init + dtype detect in one pass --------
__global__ void k_init0det(const void* edges) {
    int i = blockIdx.x * blockDim.x + threadIdx.x;   // grid covers EE
    if (i < NN) g_deg[i] = 1;                        // self loop
    const long long* p = (const long long*)edges;
    long long v = p[i];
    if (v < 0 || v >= NN) g_notI64 = 1;
}

__global__ void k_perm_int(const void* permp) {
    int i = blockIdx.x * blockDim.x + threadIdx.x;
    if (i < NN) g_permI[i] = idx_at(permp, i, !g_notI64);
}

__global__ void k_deg_count(const void* edges) {
    int e = blockIdx.x * blockDim.x + threadIdx.x;
    if (e >= EE) return;
    atomicAdd(&g_deg[idx_at(edges, EE + e, !g_notI64)], 1);
}
__global__ void k_dinv() {
    int i = blockIdx.x * blockDim.x + threadIdx.x;
    if (i < NN) g_dinv[i] = rsqrtf((float)g_deg[i]);
}

// ---------------- CSR offsets: single-block scan --------------------
__global__ void k_scan() {
    __shared__ int partial[256];
    int t = threadIdx.x;
    int base = t * 32;
    int local[32];
    int sum = 0;
#pragma unroll
    for (int j = 0; j < 32; j++) {
        int c = g_deg[base + j] - 1;
        local[j] = sum;
        sum += c;
    }
    partial[t] = sum;
    __syncthreads();
    for (int o = 1; o < 256; o <<= 1) {
        int u = (t >= o) ? partial[t - o] : 0;
        __syncthreads();
        partial[t] += u;
        __syncthreads();
    }
    int off0 = partial[t] - sum;
#pragma unroll
    for (int j = 0; j < 32; j++) {
        int o = off0 + local[j];
        g_off[base + j]  = o;
        g_fill[base + j] = o;
    }
    if (t == 255) g_off[NN] = partial[255];
}

__global__ void k_fill(const void* edges) {
    int e = blockIdx.x * blockDim.x + threadIdx.x;
    if (e >= EE) return;
    int is64 = !g_notI64;
    int s = idx_at(edges, e, is64);
    int d = idx_at(edges, EE + e, is64);
    int pos = atomicAdd(&g_fill[d], 1);
    g_csr_src [pos] = s;
    g_csr_psrc[pos] = g_permI[s];
    g_csr_nm  [pos] = g_dinv[s] * g_dinv[d];
}

// ---------------- GEMM1: [8192,3000]@[3000,256], f32x2 -------------
// 64x128 tile, BK=8, 128 threads, 8x8 f32 microtile.
// Crossbar-balanced warp mapping: ty=tid&7 (8 M/warp), tx=tid>>3
// (4 N/warp) -> distinct LDS bytes/warp/kk = 256(A)+256(B) = 512
// (2.1x less than the 2x16 mapping that measured L1=77%).
__global__ void __launch_bounds__(128, 2)
k_gemm1(const float* __restrict__ A, const float* __restrict__ B) {
    __shared__ float As[2][8][64];
    __shared__ float Bs[2][8][128];
    int tid = threadIdx.x;
    int m0 = blockIdx.y * 64;
    int n0 = blockIdx.x * 128;
    int ty = tid & 7, tx = tid >> 3;        // 8 x 16, warp spans 8 ty x 4 tx
    int ar = tid >> 1, ak = (tid & 1) * 4;  // A: 64 rows x 8k / 128 thr
    int br = tid >> 4, bc = (tid & 15) * 8; // B: 8 rows x 128 / 128 thr
    const float* Aptr = A + (size_t)(m0 + ar) * IND + ak;
    const float* Bptr = B + (size_t)br * H1D + n0 + bc;

    u64 acc[8][4];
#pragma unroll
    for (int i = 0; i < 8; i++)
#pragma unroll
        for (int j = 0; j < 4; j++) acc[i][j] = 0ull;

    float4 a0 = *(const float4*)Aptr;
    float4 b0 = *(const float4*)Bptr;
    float4 b1 = *(const float4*)(Bptr + 4);
    As[0][ak+0][ar] = a0.x; As[0][ak+1][ar] = a0.y;
    As[0][ak+2][ar] = a0.z; As[0][ak+3][ar] = a0.w;
    *(float4*)&Bs[0][br][bc]   = b0;
    *(float4*)&Bs[0][br][bc+4] = b1;
    __syncthreads();

    int buf = 0;
    for (int k0 = 8; k0 < IND; k0 += 8) {
        float4 an  = *(const float4*)(Aptr + k0);
        float4 bn0 = *(const float4*)(Bptr + (size_t)k0 * H1D);
        float4 bn1 = *(const float4*)(Bptr + (size_t)k0 * H1D + 4);
#pragma unroll
        for (int kk = 0; kk < 8; kk++) {
            float ra[8];
            *(float4*)&ra[0] = *(const float4*)&As[buf][kk][ty*8];
            *(float4*)&ra[4] = *(const float4*)&As[buf][kk][ty*8+4];
            ulonglong2 rb01 = *(const ulonglong2*)&Bs[buf][kk][tx*8];
            ulonglong2 rb23 = *(const ulonglong2*)&Bs[buf][kk][tx*8+4];
#pragma unroll
            for (int i = 0; i < 8; i++) {
                u64 aa = pack2(ra[i]);
                fma2(acc[i][0], aa, rb01.x);
                fma2(acc[i][1], aa, rb01.y);
                fma2(acc[i][2], aa, rb23.x);
                fma2(acc[i][3], aa, rb23.y);
            }
        }
        buf ^= 1;
        As[buf][ak+0][ar] = an.x; As[buf][ak+1][ar] = an.y;
        As[buf][ak+2][ar] = an.z; As[buf][ak+3][ar] = an.w;
        *(float4*)&Bs[buf][br][bc]   = bn0;
        *(float4*)&Bs[buf][br][bc+4] = bn1;
        __syncthreads();
    }
#pragma unroll
    for (int kk = 0; kk < 8; kk++) {
        float ra[8];
        *(float4*)&ra[0] = *(const float4*)&As[buf][kk][ty*8];
        *(float4*)&ra[4] = *(const float4*)&As[buf][kk][ty*8+4];
        ulonglong2 rb01 = *(const ulonglong2*)&Bs[buf][kk][tx*8];
        ulonglong2 rb23 = *(const ulonglong2*)&Bs[buf][kk][tx*8+4];
#pragma unroll
        for (int i = 0; i < 8; i++) {
            u64 aa = pack2(ra[i]);
            fma2(acc[i][0], aa, rb01.x);
            fma2(acc[i][1], aa, rb01.y);
            fma2(acc[i][2], aa, rb23.x);
            fma2(acc[i][3], aa, rb23.y);
        }
    }

#pragma unroll
    for (int i = 0; i < 8; i++) {
        float* o = &g_XW[(size_t)(m0 + ty*8 + i) * H1D + n0 + tx*8];
        ulonglong2 v01; v01.x = acc[i][0]; v01.y = acc[i][1];
        ulonglong2 v23; v23.x = acc[i][2]; v23.y = acc[i][3];
        *(ulonglong2*)o       = v01;
        *(ulonglong2*)(o + 4) = v23;
    }
}

// ---------------- conv1 gather (float4, 2 rows/block) ---------------
__global__ void k_gather1(const float* __restrict__ b1) {
    int tid = threadIdx.x;            // 128
    int i = blockIdx.x * 2 + (tid >> 6);
    int l = (tid & 63) * 4;
    float s2 = g_dinv[i] * g_dinv[i];
    int pi = g_permI[i];
    float4 x0 = *(const float4*)&g_XW[(size_t)i  * H1D + l];
    float4 xp = *(const float4*)&g_XW[(size_t)pi * H1D + l];
    float4 acc  = make_float4(s2*x0.x, s2*x0.y, s2*x0.z, s2*x0.w);
    float4 accc = make_float4(s2*xp.x, s2*xp.y, s2*xp.z, s2*xp.w);
    int e1 = g_off[i + 1];
    for (int e = g_off[i]; e < e1; e++) {
        int s  = g_csr_src[e];
        int ps = g_csr_psrc[e];
        float nm = g_csr_nm[e];
        float4 xs = *(const float4*)&g_XW[(size_t)s  * H1D + l];
        float4 xq = *(const float4*)&g_XW[(size_t)ps * H1D + l];
        acc.x  += nm*xs.x; acc.y  += nm*xs.y; acc.z  += nm*xs.z; acc.w  += nm*xs.w;
        accc.x += nm*xq.x; accc.y += nm*xq.y; accc.z += nm*xq.z; accc.w += nm*xq.w;
    }
    float4 bb = *(const float4*)&b1[l];
    float4 v;
    v.x = fmaxf(acc.x + bb.x, 0.f); v.y = fmaxf(acc.y + bb.y, 0.f);
    v.z = fmaxf(acc.z + bb.z, 0.f); v.w = fmaxf(acc.w + bb.w, 0.f);
    *(float4*)&g_H1[(size_t)i * H1D + l] = v;
    v.x = fmaxf(accc.x + bb.x, 0.f); v.y = fmaxf(accc.y + bb.y, 0.f);
    v.z = fmaxf(accc.z + bb.z, 0.f); v.w = fmaxf(accc.w + bb.w, 0.f);
    *(float4*)&g_H1c[(size_t)i * H1D + l] = v;
}

// ---------------- GEMM2: [2*8192,256]@[256,64] ----------------------
__global__ void __launch_bounds__(256, 1)
k_gemm2(const float* __restrict__ W2) {
    const float* Am = (blockIdx.x < 64) ? g_H1  : g_H1c;
    float*       Om = (blockIdx.x < 64) ? g_XW2 : g_XW2c;
    int m0 = (blockIdx.x & 63) * 128;

    __shared__ float As[2][8][128];
    __shared__ float Bs[2][8][64];
    int tid = threadIdx.x;
    int ty = tid >> 4, tx = tid & 15;
    int ar = tid >> 1, ak = (tid & 1) * 4;
    int br = tid >> 5, bc = (tid & 31) * 2;
    const float* Aptr = Am + (size_t)(m0 + ar) * H1D + ak;
    const float* Bptr = W2 + (size_t)br * H2D + bc;

    u64 acc[8][2];
#pragma unroll
    for (int i = 0; i < 8; i++) { acc[i][0] = 0ull; acc[i][1] = 0ull; }

    float4 a0 = *(const float4*)Aptr;
    float2 b0 = *(const float2*)Bptr;
    As[0][ak+0][ar] = a0.x; As[0][ak+1][ar] = a0.y;
    As[0][ak+2][ar] = a0.z; As[0][ak+3][ar] = a0.w;
    *(float2*)&Bs[0][br][bc] = b0;
    __syncthreads();

    int buf = 0;
    for (int k0 = 8; k0 < H1D; k0 += 8) {
        float4 an = *(const float4*)(Aptr + k0);
        float2 bn = *(const float2*)(Bptr + (size_t)k0 * H2D);
#pragma unroll
        for (int kk = 0; kk < 8; kk++) {
            float ra[8];
            *(float4*)&ra[0] = *(const float4*)&As[buf][kk][ty*8];
            *(float4*)&ra[4] = *(const float4*)&As[buf][kk][ty*8+4];
            ulonglong2 rb = *(const ulonglong2*)&Bs[buf][kk][tx*4];
#pragma unroll
            for (int i = 0; i < 8; i++) {
                u64 aa = pack2(ra[i]);
                fma2(acc[i][0], aa, rb.x);
                fma2(acc[i][1], aa, rb.y);
            }
        }
        buf ^= 1;
        As[buf][ak+0][ar] = an.x; As[buf][ak+1][ar] = an.y;
        As[buf][ak+2][ar] = an.z; As[buf][ak+3][ar] = an.w;
        *(float2*)&Bs[buf][br][bc] = bn;
        __syncthreads();
    }
#pragma unroll
    for (int kk = 0; kk < 8; kk++) {
        float ra[8];
        *(float4*)&ra[0] = *(const float4*)&As[buf][kk][ty*8];
        *(float4*)&ra[4] = *(const float4*)&As[buf][kk][ty*8+4];
        ulonglong2 rb = *(const ulonglong2*)&Bs[buf][kk][tx*4];
#pragma unroll
        for (int i = 0; i < 8; i++) {
            u64 aa = pack2(ra[i]);
            fma2(acc[i][0], aa, rb.x);
            fma2(acc[i][1], aa, rb.y);
        }
    }

#pragma unroll
    for (int i = 0; i < 8; i++) {
        ulonglong2 v; v.x = acc[i][0]; v.y = acc[i][1];
        *(ulonglong2*)&Om[(size_t)(m0 + ty*8 + i) * H2D + tx*4] = v;
    }
}

// ---------------- conv2 gather (float4, 16 rows/block) --------------
__global__ void k_gather2(const float* __restrict__ b2, float* __restrict__ out_x1) {
    int t = threadIdx.x;            // 256
    int i = blockIdx.x * 16 + (t >> 4);
    int l = (t & 15) * 4;
    float s2 = g_dinv[i] * g_dinv[i];
    float4 x0 = *(const float4*)&g_XW2 [(size_t)i * H2D + l];
    float4 xc = *(const float4*)&g_XW2c[(size_t)i * H2D + l];
    float4 acc  = make_float4(s2*x0.x, s2*x0.y, s2*x0.z, s2*x0.w);
    float4 accc = make_float4(s2*xc.x, s2*xc.y, s2*xc.z, s2*xc.w);
    int e1 = g_off[i + 1];
    for (int e = g_off[i]; e < e1; e++) {
        int s = g_csr_src[e];
        float nm = g_csr_nm[e];
        float4 xs = *(const float4*)&g_XW2 [(size_t)s * H2D + l];
        float4 xq = *(const float4*)&g_XW2c[(size_t)s * H2D + l];
        acc.x  += nm*xs.x; acc.y  += nm*xs.y; acc.z  += nm*xs.z; acc.w  += nm*xs.w;
        accc.x += nm*xq.x; accc.y += nm*xq.y; accc.z += nm*xq.z; accc.w += nm*xq.w;
    }
    float4 bb = *(const float4*)&b2[l];
    float4 v;
    v.x = fmaxf(acc.x + bb.x, 0.f); v.y = fmaxf(acc.y + bb.y, 0.f);
    v.z = fmaxf(acc.z + bb.z, 0.f); v.w = fmaxf(acc.w + bb.w, 0.f);
    *(float4*)&out_x1[(size_t)i * H2D + l] = v;
    v.x = fmaxf(accc.x + bb.x, 0.f); v.y = fmaxf(accc.y + bb.y, 0.f);
    v.z = fmaxf(accc.z + bb.z, 0.f); v.w = fmaxf(accc.w + bb.w, 0.f);
    *(float4*)&g_X2c[(size_t)i * H2D + l] = v;
}

// ---------------- readout: compact nnz, then coalesced gather -------
__global__ void k_readout(const float* __restrict__ mask, const float* __restrict__ x1) {
    __shared__ int   s_idx[1024];
    __shared__ float s_val[1024];
    __shared__ int   s_cnt;
    __shared__ float s_rs;
    __shared__ float part1[4][H2D], part2[4][H2D];
    __shared__ float vs1[H2D], vs2[H2D];
    __shared__ float nrm1, nrm2;
    int i = blockIdx.x;
    int tid = threadIdx.x;  // 256
    if (tid == 0) { s_cnt = 0; s_rs = 0.f; }
    __syncthreads();

    float rs = 0.f;
    const float4* m4 = (const float4*)&mask[(size_t)i * NN];
    for (int j4 = tid; j4 < NN / 4; j4 += 256) {
        float4 m = m4[j4];
        rs += m.x + m.y + m.z + m.w;
        if (m.x != 0.f) { int p = atomicAdd(&s_cnt, 1); if (p < 1024) { s_idx[p] = j4*4;   s_val[p] = m.x; } }
        if (m.y != 0.f) { int p = atomicAdd(&s_cnt, 1); if (p < 1024) { s_idx[p] = j4*4+1; s_val[p] = m.y; } }
        if (m.z != 0.f) { int p = atomicAdd(&s_cnt, 1); if (p < 1024) { s_idx[p] = j4*4+2; s_val[p] = m.z; } }
        if (m.w != 0.f) { int p = atomicAdd(&s_cnt, 1); if (p < 1024) { s_idx[p] = j4*4+3; s_val[p] = m.w; } }
    }
#pragma unroll
    for (int o = 16; o; o >>= 1) rs += __shfl_down_sync(0xFFFFFFFFu, rs, o);
    if ((tid & 31) == 0) atomicAdd(&s_rs, rs);
    __syncthreads();

    int cnt = s_cnt < 1024 ? s_cnt : 1024;
    int g = tid >> 6, f = tid & 63;
    float a1 = 0.f, a2 = 0.f;
    for (int e = g; e < cnt; e += 4) {
        int j = s_idx[e];
        float mv = s_val[e];
        a1 += mv * x1   [(size_t)j * H2D + f];
        a2 += mv * g_X2c[(size_t)j * H2D + f];
    }
    part1[g][f] = a1;
    part2[g][f] = a2;
    __syncthreads();

    if (tid < H2D) {
        float inv = 1.0f / s_rs;
        vs1[tid] = (part1[0][tid] + part1[1][tid] + part1[2][tid] + part1[3][tid]) * inv;
        vs2[tid] = (part2[0][tid] + part2[1][tid] + part2[2][tid] + part2[3][tid]) * inv;
    }
    __syncthreads();
    if (tid == 0) {
        float s1 = 0.f, s2 = 0.f;
        for (int q = 0; q < H2D; q++) { s1 += vs1[q]*vs1[q]; s2 += vs2[q]*vs2[q]; }
        nrm1 = fmaxf(sqrtf(s1), 1e-12f);
        nrm2 = fmaxf(sqrtf(s2), 1e-12f);
    }
    __syncthreads();
    if (tid < H2D) {
        float v1 = vs1[tid] / nrm1;
        float v2 = vs2[tid] / nrm2;
        g_G1 [i*H2D + tid] = 1.0f / (1.0f + expf(-v1));
        g_G1c[i*H2D + tid] = 1.0f / (1.0f + expf(-v2));
    }
}

// ---------------- bilinear discriminator ----------------
__global__ void k_bilinear(const float* __restrict__ Wd, const float* __restrict__ bd,
                           const float* __restrict__ x1,
                           float* __restrict__ ret1, float* __restrict__ ret1c) {
    __shared__ float c1[H2D], c2[H2D], h[H2D], hc[H2D];
    __shared__ float red[4][H2D];
    int i = blockIdx.x;
    int k = threadIdx.x;  // 64
    c1[k] = g_G1 [i*H2D + k];
    c2[k] = g_G1c[i*H2D + k];
    h [k] = x1   [(size_t)i*H2D + k];
    hc[k] = g_X2c[(size_t)i*H2D + k];
    __syncthreads();
    float t1 = 0.f, t2 = 0.f;
    const float4* wr = (const float4*)&Wd[k * H2D];
#pragma unroll
    for (int j4 = 0; j4 < H2D / 4; j4++) {
        float4 w = wr[j4];
        t1 += w.x*c1[j4*4] + w.y*c1[j4*4+1] + w.z*c1[j4*4+2] + w.w*c1[j4*4+3];
        t2 += w.x*c2[j4*4] + w.y*c2[j4*4+1] + w.z*c2[j4*4+2] + w.w*c2[j4*4+3];
    }
    red[0][k] = h [k] * t1;
    red[1][k] = hc[k] * t1;
    red[2][k] = hc[k] * t2;
    red[3][k] = h [k] * t2;
    __syncthreads();
    if (k < 4) {
        float s = 0.f;
        for (int j = 0; j < H2D; j++) s += red[k][j];
        s += bd[0];
        if (k == 0) ret1 [i*2 + 0] = s;
        if (k == 1) ret1 [i*2 + 1] = s;
        if (k == 2) ret1c[i*2 + 0] = s;
        if (k == 3) ret1c[i*2 + 1] = s;
    }
}

// ---------------- launch ----------------
extern "C" void kernel_launch(void* const* d_in, const int* in_sizes, int n_in,
                              void* d_out, int out_size) {
    const float* gene = (const float*)d_in[0];
    const float* mask = (const float*)d_in[1];
    const float* W1   = (const float*)d_in[2];
    const float* b1   = (const float*)d_in[3];
    const float* W2   = (const float*)d_in[4];
    const float* b2   = (const float*)d_in[5];
    const float* Wd   = (const float*)d_in[6];
    const float* bd   = (const float*)d_in[7];
    const void*  edges = d_in[8];
    const void*  perm  = d_in[9];

    float* out    = (float*)d_out;
    float* out_x1 = out;
    float* out_r1 = out + NN * H2D;
    float* out_rc = out + NN * H2D + NN * 2;

    k_init0det <<<EE / 256, 256>>>(edges);
    k_perm_int <<<NN / 256, 256>>>(perm);
    k_deg_count<<<EE / 256, 256>>>(edges);

    dim3 gg1(H1D / 128, NN / 64);    // (2, 128) = 256 CTAs — launch #4 (profiled)
    k_gemm1    <<<gg1, 128>>>(gene, W1);

    k_dinv     <<<NN / 256, 256>>>();
    k_scan     <<<1, 256>>>();
    k_fill     <<<EE / 256, 256>>>(edges);

    k_gather1  <<<NN / 2, 128>>>(b1);
    k_gemm2    <<<128, 256>>>(W2);
    k_gather2  <<<NN / 16, 256>>>(b2, out_x1);

    k_readout  <<<NN, 256>>>(mask, out_x1);
    k_bilinear <<<NN, 64>>>(Wd, bd, out_x1, out_r1, out_rc);
}

// round 12
// speedup vs baseline: 1.5086x; 1.4969x over previous
#include <cuda_runtime.h>
#include <cuda_bf16.h>
#include <math.h>

#define NN   8192
#define EE   131072
#define IND  3000
#define H1D  256
#define H2D  64
#define KPAD 3008            // 94 * 32
#define CH   32              // K per smem stage
#define NST  (KPAD/CH)       // 94
#define SROW 40              // smem row stride in bf16 (80B: conflict-free ldmatrix)
#define MATB (128*SROW*2)    // 10240 B per 128-row matrix
#define STAGEB (4*MATB)      // 40960 B per stage (Ah,Al,Bh,Bl)

typedef unsigned long long u64;
typedef unsigned u32;

// ---------------- scratch ----------------
__device__ float g_XW   [NN*H1D];
__device__ float g_H1   [NN*H1D];
__device__ float g_H1c  [NN*H1D];
__device__ float g_XW2  [NN*H2D];
__device__ float g_XW2c [NN*H2D];
__device__ float g_X2c  [NN*H2D];
__device__ float g_G1   [NN*H2D];
__device__ float g_G1c  [NN*H2D];
__device__ float g_dinv [NN];
__device__ int   g_deg  [NN];
__device__ int   g_off  [NN+1];
__device__ int   g_fill [NN];
__device__ int   g_permI[NN];
__device__ int   g_csr_src [EE];
__device__ int   g_csr_psrc[EE];
__device__ float g_csr_nm  [EE];
__device__ int   g_notI64;            // zero at load; set deterministically
__device__ __nv_bfloat16 g_Ah[(size_t)NN*KPAD];
__device__ __nv_bfloat16 g_Al[(size_t)NN*KPAD];
__device__ __nv_bfloat16 g_Bh[(size_t)H1D*KPAD];
__device__ __nv_bfloat16 g_Bl[(size_t)H1D*KPAD];

// ---------------- helpers ----------------
__device__ __forceinline__ u64 pack2(float x) {
    u64 r; asm("mov.b64 %0, {%1, %1};" : "=l"(r) : "f"(x)); return r;
}
__device__ __forceinline__ void fma2(u64& d, u64 a, u64 b) {
    asm("fma.rn.f32x2 %0, %1, %2, %0;" : "+l"(d) : "l"(a), "l"(b));
}
__device__ __forceinline__ u32 smem_u32(const void* p) {
    u32 a;
    asm("{ .reg .u64 t; cvta.to.shared.u64 t, %1; cvt.u32.u64 %0, t; }"
        : "=r"(a) : "l"(p));
    return a;
}
__device__ __forceinline__ void ldm_x4(u32* r, u32 addr) {
    asm volatile("ldmatrix.sync.aligned.m8n8.x4.shared.b16 {%0,%1,%2,%3}, [%4];"
                 : "=r"(r[0]), "=r"(r[1]), "=r"(r[2]), "=r"(r[3]) : "r"(addr));
}
__device__ __forceinline__ void mma_bf16(float* d, const u32* a, u32 b0, u32 b1) {
    asm volatile(
        "mma.sync.aligned.m16n8k16.row.col.f32.bf16.bf16.f32 "
        "{%0,%1,%2,%3}, {%4,%5,%6,%7}, {%8,%9}, {%0,%1,%2,%3};"
        : "+f"(d[0]), "+f"(d[1]), "+f"(d[2]), "+f"(d[3])
        : "r"(a[0]), "r"(a[1]), "r"(a[2]), "r"(a[3]), "r"(b0), "r"(b1));
}
__device__ __forceinline__ int idx_at(const void* p, int i, int is64) {
    return is64 ? (int)((const long long*)p)[i] : ((const int*)p)[i];
}

// ---------------- setup: deg init + dtype detect --------------------
__global__ void k_init0det(const void* edges) {
    int i = blockIdx.x * blockDim.x + threadIdx.x;   // grid covers EE
    if (i < NN) g_deg[i] = 1;
    const long long* p = (const long long*)edges;
    long long v = p[i];
    if (v < 0 || v >= NN) g_notI64 = 1;
}

// ---------------- bf16 hi/lo split conversions ----------------------
__global__ void k_convA(const float* __restrict__ A) {
    int idx = blockIdx.x * 256 + threadIdx.x;        // NN * (KPAD/8)
    int m = idx / (KPAD/8), g = idx % (KPAD/8);
    int k = g * 8;
    __align__(16) __nv_bfloat16 h[8], l[8];
    if (k < IND) {                                    // 3000/8 = 375 full groups
        const float* p = A + (size_t)m * IND + k;
#pragma unroll
        for (int j = 0; j < 8; j++) {
            float v = p[j];
            __nv_bfloat16 hh = __float2bfloat16(v);
            h[j] = hh;
            l[j] = __float2bfloat16(v - __bfloat162float(hh));
        }
    } else {
#pragma unroll
        for (int j = 0; j < 8; j++) { h[j] = __float2bfloat16(0.f); l[j] = h[j]; }
    }
    *(uint4*)&g_Ah[(size_t)m * KPAD + k] = *(uint4*)h;
    *(uint4*)&g_Al[(size_t)m * KPAD + k] = *(uint4*)l;
}

__global__ void k_convB(const float* __restrict__ W1) {
    int idx = blockIdx.x * 256 + threadIdx.x;        // H1D * (KPAD/8)
    int n = idx / (KPAD/8), g = idx % (KPAD/8);
    int k = g * 8;
    __align__(16) __nv_bfloat16 h[8], l[8];
#pragma unroll
    for (int j = 0; j < 8; j++) {
        int kk = k + j;
        float v = (kk < IND) ? W1[(size_t)kk * H1D + n] : 0.f;
        __nv_bfloat16 hh = __float2bfloat16(v);
        h[j] = hh;
        l[j] = __float2bfloat16(v - __bfloat162float(hh));
    }
    *(uint4*)&g_Bh[(size_t)n * KPAD + k] = *(uint4*)h;
    *(uint4*)&g_Bl[(size_t)n * KPAD + k] = *(uint4*)l;
}

// ---------------- GEMM1 via mma.sync bf16 (3-term split) -----------
// CTA 128x128, 8 warps (warp tile 64x32), K-stage 32, double buffer.
// D = Ah*Bh + Ah*Bl + Al*Bh, fp32 accum.
__global__ void __launch_bounds__(256)
k_gemm1_tc() {
    extern __shared__ char smem[];
    u32 sb = smem_u32(smem);
    int tid = threadIdx.x;
    int wid = tid >> 5, lane = tid & 31;
    int wm = wid & 1, wn = wid >> 1;        // warp grid 2(M) x 4(N)
    int m0 = blockIdx.y * 128;
    int n0 = blockIdx.x * 128;

    // global load descriptors: 8 uint4 per thread per stage
    // idx = q*256+tid: mat = idx/512 (0:Ah 1:Al 2:Bh 3:Bl), r=(idx%512)/4, kq=idx%4
    const __nv_bfloat16* gsrc[4];
    u32 sdst[8];
    size_t goff[8];
#pragma unroll
    for (int q = 0; q < 8; q++) {
        int idx = q * 256 + tid;
        int mat = idx >> 9, rem = idx & 511;
        int r = rem >> 2, kq = rem & 3;
        sdst[q] = mat * MATB + r * (SROW*2) + kq * 16;
        int grow = (mat < 2) ? (m0 + r) : (n0 + r);
        goff[q] = (size_t)grow * KPAD + kq * 8;
        gsrc[mat] = (mat == 0) ? g_Ah : (mat == 1) ? g_Al : (mat == 2) ? g_Bh : g_Bl;
    }
    const __nv_bfloat16* gm[8];
#pragma unroll
    for (int q = 0; q < 8; q++) gm[q] = gsrc[(q * 256 + tid) >> 9];

    // ldmatrix lane address bases (byte offsets within a matrix)
    u32 aBase = (u32)((wm*64 + (lane & 15)) * (SROW*2) + (lane >> 4) * 16);
    u32 bBase = (u32)((wn*32 + ((lane >> 4) * 8) + (lane & 7)) * (SROW*2)
                      + ((lane >> 3) & 1) * 16);

    float acc[4][4][4];
#pragma unroll
    for (int i = 0; i < 4; i++)
#pragma unroll
        for (int j = 0; j < 4; j++)
#pragma unroll
            for (int q = 0; q < 4; q++) acc[i][j][q] = 0.f;

    // preload stage 0
#pragma unroll
    for (int q = 0; q < 8; q++)
        *(uint4*)(smem + sdst[q]) = *(const uint4*)&gm[q][goff[q]];
    __syncthreads();

    for (int c = 0; c < NST; c++) {
        int b = c & 1;
        uint4 v[8];
        if (c + 1 < NST) {
            size_t ko = (size_t)(c + 1) * CH;
#pragma unroll
            for (int q = 0; q < 8; q++) v[q] = *(const uint4*)&gm[q][goff[q] + ko];
        }
        u32 bufb = sb + b * STAGEB;
#pragma unroll
        for (int ks = 0; ks < 2; ks++) {
            u32 ko = ks * 32;                 // 16 bf16 = 32 bytes
            u32 ah[4][4], al[4][4], bh[2][4], bl[2][4];
#pragma unroll
            for (int mt = 0; mt < 4; mt++) {
                u32 ao = bufb + aBase + mt * (16*SROW*2) + ko;
                ldm_x4(ah[mt], ao);
                ldm_x4(al[mt], ao + MATB);
            }
#pragma unroll
            for (int t = 0; t < 2; t++) {
                u32 bo = bufb + 2*MATB + bBase + t * (16*SROW*2) + ko;
                ldm_x4(bh[t], bo);
                ldm_x4(bl[t], bo + MATB);
            }
#pragma unroll
            for (int mt = 0; mt < 4; mt++)
#pragma unroll
                for (int nt = 0; nt < 4; nt++) {
                    int t = nt >> 1, s = (nt & 1) * 2;
                    mma_bf16(acc[mt][nt], ah[mt], bh[t][s], bh[t][s+1]);
                    mma_bf16(acc[mt][nt], ah[mt], bl[t][s], bl[t][s+1]);
                    mma_bf16(acc[mt][nt], al[mt], bh[t][s], bh[t][s+1]);
                }
        }
        if (c + 1 < NST) {
            int nb = b ^ 1;
#pragma unroll
            for (int q = 0; q < 8; q++)
                *(uint4*)(smem + nb * STAGEB + sdst[q]) = v[q];
        }
        __syncthreads();
    }

    // epilogue: m16n8 accum layout: c0,c1 -> (row lane/4, col (lane%4)*2,+1);
    //           c2,c3 -> row+8
    int er = lane >> 2, ec = (lane & 3) * 2;
#pragma unroll
    for (int mt = 0; mt < 4; mt++) {
#pragma unroll
        for (int nt = 0; nt < 4; nt++) {
            int row = m0 + wm*64 + mt*16 + er;
            int col = n0 + wn*32 + nt*8 + ec;
            *(float2*)&g_XW[(size_t)row * H1D + col] =
                make_float2(acc[mt][nt][0], acc[mt][nt][1]);
            *(float2*)&g_XW[(size_t)(row + 8) * H1D + col] =
                make_float2(acc[mt][nt][2], acc[mt][nt][3]);
        }
    }
}

// ---------------- graph setup ----------------
__global__ void k_perm_int(const void* permp) {
    int i = blockIdx.x * blockDim.x + threadIdx.x;
    if (i < NN) g_permI[i] = idx_at(permp, i, !g_notI64);
}
__global__ void k_deg_count(const void* edges) {
    int e = blockIdx.x * blockDim.x + threadIdx.x;
    if (e >= EE) return;
    atomicAdd(&g_deg[idx_at(edges, EE + e, !g_notI64)], 1);
}
__global__ void k_dinv() {
    int i = blockIdx.x * blockDim.x + threadIdx.x;
    if (i < NN) g_dinv[i] = rsqrtf((float)g_deg[i]);
}
__global__ void k_scan() {
    __shared__ int partial[256];
    int t = threadIdx.x;
    int base = t * 32;
    int local[32];
    int sum = 0;
#pragma unroll
    for (int j = 0; j < 32; j++) {
        int c = g_deg[base + j] - 1;
        local[j] = sum;
        sum += c;
    }
    partial[t] = sum;
    __syncthreads();
    for (int o = 1; o < 256; o <<= 1) {
        int u = (t >= o) ? partial[t - o] : 0;
        __syncthreads();
        partial[t] += u;
        __syncthreads();
    }
    int off0 = partial[t] - sum;
#pragma unroll
    for (int j = 0; j < 32; j++) {
        int o = off0 + local[j];
        g_off[base + j]  = o;
        g_fill[base + j] = o;
    }
    if (t == 255) g_off[NN] = partial[255];
}
__global__ void k_fill(const void* edges) {
    int e = blockIdx.x * blockDim.x + threadIdx.x;
    if (e >= EE) return;
    int is64 = !g_notI64;
    int s = idx_at(edges, e, is64);
    int d = idx_at(edges, EE + e, is64);
    int pos = atomicAdd(&g_fill[d], 1);
    g_csr_src [pos] = s;
    g_csr_psrc[pos] = g_permI[s];
    g_csr_nm  [pos] = g_dinv[s] * g_dinv[d];
}

// ---------------- conv1 gather ----------------
__global__ void k_gather1(const float* __restrict__ b1) {
    int tid = threadIdx.x;            // 128
    int i = blockIdx.x * 2 + (tid >> 6);
    int l = (tid & 63) * 4;
    float s2 = g_dinv[i] * g_dinv[i];
    int pi = g_permI[i];
    float4 x0 = *(const float4*)&g_XW[(size_t)i  * H1D + l];
    float4 xp = *(const float4*)&g_XW[(size_t)pi * H1D + l];
    float4 acc  = make_float4(s2*x0.x, s2*x0.y, s2*x0.z, s2*x0.w);
    float4 accc = make_float4(s2*xp.x, s2*xp.y, s2*xp.z, s2*xp.w);
    int e1 = g_off[i + 1];
    for (int e = g_off[i]; e < e1; e++) {
        int s  = g_csr_src[e];
        int ps = g_csr_psrc[e];
        float nm = g_csr_nm[e];
        float4 xs = *(const float4*)&g_XW[(size_t)s  * H1D + l];
        float4 xq = *(const float4*)&g_XW[(size_t)ps * H1D + l];
        acc.x  += nm*xs.x; acc.y  += nm*xs.y; acc.z  += nm*xs.z; acc.w  += nm*xs.w;
        accc.x += nm*xq.x; accc.y += nm*xq.y; accc.z += nm*xq.z; accc.w += nm*xq.w;
    }
    float4 bb = *(const float4*)&b1[l];
    float4 v;
    v.x = fmaxf(acc.x + bb.x, 0.f); v.y = fmaxf(acc.y + bb.y, 0.f);
    v.z = fmaxf(acc.z + bb.z, 0.f); v.w = fmaxf(acc.w + bb.w, 0.f);
    *(float4*)&g_H1[(size_t)i * H1D + l] = v;
    v.x = fmaxf(accc.x + bb.x, 0.f); v.y = fmaxf(accc.y + bb.y, 0.f);
    v.z = fmaxf(accc.z + bb.z, 0.f); v.w = fmaxf(accc.w + bb.w, 0.f);
    *(float4*)&g_H1c[(size_t)i * H1D + l] = v;
}

// ---------------- GEMM2: [2*8192,256]@[256,64] ----------------------
__global__ void __launch_bounds__(256, 1)
k_gemm2(const float* __restrict__ W2) {
    const float* Am = (blockIdx.x < 64) ? g_H1  : g_H1c;
    float*       Om = (blockIdx.x < 64) ? g_XW2 : g_XW2c;
    int m0 = (blockIdx.x & 63) * 128;

    __shared__ float As[2][8][128];
    __shared__ float Bs[2][8][64];
    int tid = threadIdx.x;
    int ty = tid >> 4, tx = tid & 15;
    int ar = tid >> 1, ak = (tid & 1) * 4;
    int br = tid >> 5, bc = (tid & 31) * 2;
    const float* Aptr = Am + (size_t)(m0 + ar) * H1D + ak;
    const float* Bptr = W2 + (size_t)br * H2D + bc;

    u64 acc[8][2];
#pragma unroll
    for (int i = 0; i < 8; i++) { acc[i][0] = 0ull; acc[i][1] = 0ull; }

    float4 a0 = *(const float4*)Aptr;
    float2 b0 = *(const float2*)Bptr;
    As[0][ak+0][ar] = a0.x; As[0][ak+1][ar] = a0.y;
    As[0][ak+2][ar] = a0.z; As[0][ak+3][ar] = a0.w;
    *(float2*)&Bs[0][br][bc] = b0;
    __syncthreads();

    int buf = 0;
    for (int k0 = 8; k0 < H1D; k0 += 8) {
        float4 an = *(const float4*)(Aptr + k0);
        float2 bn = *(const float2*)(Bptr + (size_t)k0 * H2D);
#pragma unroll
        for (int kk = 0; kk < 8; kk++) {
            float ra[8];
            *(float4*)&ra[0] = *(const float4*)&As[buf][kk][ty*8];
            *(float4*)&ra[4] = *(const float4*)&As[buf][kk][ty*8+4];
            ulonglong2 rb = *(const ulonglong2*)&Bs[buf][kk][tx*4];
#pragma unroll
            for (int i = 0; i < 8; i++) {
                u64 aa = pack2(ra[i]);
                fma2(acc[i][0], aa, rb.x);
                fma2(acc[i][1], aa, rb.y);
            }
        }
        buf ^= 1;
        As[buf][ak+0][ar] = an.x; As[buf][ak+1][ar] = an.y;
        As[buf][ak+2][ar] = an.z; As[buf][ak+3][ar] = an.w;
        *(float2*)&Bs[buf][br][bc] = bn;
        __syncthreads();
    }
#pragma unroll
    for (int kk = 0; kk < 8; kk++) {
        float ra[8];
        *(float4*)&ra[0] = *(const float4*)&As[buf][kk][ty*8];
        *(float4*)&ra[4] = *(const float4*)&As[buf][kk][ty*8+4];
        ulonglong2 rb = *(const ulonglong2*)&Bs[buf][kk][tx*4];
#pragma unroll
        for (int i = 0; i < 8; i++) {
            u64 aa = pack2(ra[i]);
            fma2(acc[i][0], aa, rb.x);
            fma2(acc[i][1], aa, rb.y);
        }
    }

#pragma unroll
    for (int i = 0; i < 8; i++) {
        ulonglong2 v; v.x = acc[i][0]; v.y = acc[i][1];
        *(ulonglong2*)&Om[(size_t)(m0 + ty*8 + i) * H2D + tx*4] = v;
    }
}

// ---------------- conv2 gather ----------------
__global__ void k_gather2(const float* __restrict__ b2, float* __restrict__ out_x1) {
    int t = threadIdx.x;            // 256
    int i = blockIdx.x * 16 + (t >> 4);
    int l = (t & 15) * 4;
    float s2 = g_dinv[i] * g_dinv[i];
    float4 x0 = *(const float4*)&g_XW2 [(size_t)i * H2D + l];
    float4 xc = *(const float4*)&g_XW2c[(size_t)i * H2D + l];
    float4 acc  = make_float4(s2*x0.x, s2*x0.y, s2*x0.z, s2*x0.w);
    float4 accc = make_float4(s2*xc.x, s2*xc.y, s2*xc.z, s2*xc.w);
    int e1 = g_off[i + 1];
    for (int e = g_off[i]; e < e1; e++) {
        int s = g_csr_src[e];
        float nm = g_csr_nm[e];
        float4 xs = *(const float4*)&g_XW2 [(size_t)s * H2D + l];
        float4 xq = *(const float4*)&g_XW2c[(size_t)s * H2D + l];
        acc.x  += nm*xs.x; acc.y  += nm*xs.y; acc.z  += nm*xs.z; acc.w  += nm*xs.w;
        accc.x += nm*xq.x; accc.y += nm*xq.y; accc.z += nm*xq.z; accc.w += nm*xq.w;
    }
    float4 bb = *(const float4*)&b2[l];
    float4 v;
    v.x = fmaxf(acc.x + bb.x, 0.f); v.y = fmaxf(acc.y + bb.y, 0.f);
    v.z = fmaxf(acc.z + bb.z, 0.f); v.w = fmaxf(acc.w + bb.w, 0.f);
    *(float4*)&out_x1[(size_t)i * H2D + l] = v;
    v.x = fmaxf(accc.x + bb.x, 0.f); v.y = fmaxf(accc.y + bb.y, 0.f);
    v.z = fmaxf(accc.z + bb.z, 0.f); v.w = fmaxf(accc.w + bb.w, 0.f);
    *(float4*)&g_X2c[(size_t)i * H2D + l] = v;
}

// ---------------- readout ----------------
__global__ void k_readout(const float* __restrict__ mask, const float* __restrict__ x1) {
    __shared__ int   s_idx[1024];
    __shared__ float s_val[1024];
    __shared__ int   s_cnt;
    __shared__ float s_rs;
    __shared__ float part1[4][H2D], part2[4][H2D];
    __shared__ float vs1[H2D], vs2[H2D];
    __shared__ float nrm1, nrm2;
    int i = blockIdx.x;
    int tid = threadIdx.x;  // 256
    if (tid == 0) { s_cnt = 0; s_rs = 0.f; }
    __syncthreads();

    float rs = 0.f;
    const float4* m4 = (const float4*)&mask[(size_t)i * NN];
    for (int j4 = tid; j4 < NN / 4; j4 += 256) {
        float4 m = m4[j4];
        rs += m.x + m.y + m.z + m.w;
        if (m.x != 0.f) { int p = atomicAdd(&s_cnt, 1); if (p < 1024) { s_idx[p] = j4*4;   s_val[p] = m.x; } }
        if (m.y != 0.f) { int p = atomicAdd(&s_cnt, 1); if (p < 1024) { s_idx[p] = j4*4+1; s_val[p] = m.y; } }
        if (m.z != 0.f) { int p = atomicAdd(&s_cnt, 1); if (p < 1024) { s_idx[p] = j4*4+2; s_val[p] = m.z; } }
        if (m.w != 0.f) { int p = atomicAdd(&s_cnt, 1); if (p < 1024) { s_idx[p] = j4*4+3; s_val[p] = m.w; } }
    }
#pragma unroll
    for (int o = 16; o; o >>= 1) rs += __shfl_down_sync(0xFFFFFFFFu, rs, o);
    if ((tid & 31) == 0) atomicAdd(&s_rs, rs);
    __syncthreads();

    int cnt = s_cnt < 1024 ? s_cnt : 1024;
    int g = tid >> 6, f = tid & 63;
    float a1 = 0.f, a2 = 0.f;
    for (int e = g; e < cnt; e += 4) {
        int j = s_idx[e];
        float mv = s_val[e];
        a1 += mv * x1   [(size_t)j * H2D + f];
        a2 += mv * g_X2c[(size_t)j * H2D + f];
    }
    part1[g][f] = a1;
    part2[g][f] = a2;
    __syncthreads();

    if (tid < H2D) {
        float inv = 1.0f / s_rs;
        vs1[tid] = (part1[0][tid] + part1[1][tid] + part1[2][tid] + part1[3][tid]) * inv;
        vs2[tid] = (part2[0][tid] + part2[1][tid] + part2[2][tid] + part2[3][tid]) * inv;
    }
    __syncthreads();
    if (tid == 0) {
        float s1 = 0.f, s2 = 0.f;
        for (int q = 0; q < H2D; q++) { s1 += vs1[q]*vs1[q]; s2 += vs2[q]*vs2[q]; }
        nrm1 = fmaxf(sqrtf(s1), 1e-12f);
        nrm2 = fmaxf(sqrtf(s2), 1e-12f);
    }
    __syncthreads();
    if (tid < H2D) {
        float v1 = vs1[tid] / nrm1;
        float v2 = vs2[tid] / nrm2;
        g_G1 [i*H2D + tid] = 1.0f / (1.0f + expf(-v1));
        g_G1c[i*H2D + tid] = 1.0f / (1.0f + expf(-v2));
    }
}

// ---------------- bilinear ----------------
__global__ void k_bilinear(const float* __restrict__ Wd, const float* __restrict__ bd,
                           const float* __restrict__ x1,
                           float* __restrict__ ret1, float* __restrict__ ret1c) {
    __shared__ float c1[H2D], c2[H2D], h[H2D], hc[H2D];
    __shared__ float red[4][H2D];
    int i = blockIdx.x;
    int k = threadIdx.x;  // 64
    c1[k] = g_G1 [i*H2D + k];
    c2[k] = g_G1c[i*H2D + k];
    h [k] = x1   [(size_t)i*H2D + k];
    hc[k] = g_X2c[(size_t)i*H2D + k];
    __syncthreads();
    float t1 = 0.f, t2 = 0.f;
    const float4* wr = (const float4*)&Wd[k * H2D];
#pragma unroll
    for (int j4 = 0; j4 < H2D / 4; j4++) {
        float4 w = wr[j4];
        t1 += w.x*c1[j4*4] + w.y*c1[j4*4+1] + w.z*c1[j4*4+2] + w.w*c1[j4*4+3];
        t2 += w.x*c2[j4*4] + w.y*c2[j4*4+1] + w.z*c2[j4*4+2] + w.w*c2[j4*4+3];
    }
    red[0][k] = h [k] * t1;
    red[1][k] = hc[k] * t1;
    red[2][k] = hc[k] * t2;
    red[3][k] = h [k] * t2;
    __syncthreads();
    if (k < 4) {
        float s = 0.f;
        for (int j = 0; j < H2D; j++) s += red[k][j];
        s += bd[0];
        if (k == 0) ret1 [i*2 + 0] = s;
        if (k == 1) ret1 [i*2 + 1] = s;
        if (k == 2) ret1c[i*2 + 0] = s;
        if (k == 3) ret1c[i*2 + 1] = s;
    }
}

// ---------------- launch ----------------
extern "C" void kernel_launch(void* const* d_in, const int* in_sizes, int n_in,
                              void* d_out, int out_size) {
    const float* gene = (const float*)d_in[0];
    const float* mask = (const float*)d_in[1];
    const float* W1   = (const float*)d_in[2];
    const float* b1   = (const float*)d_in[3];
    const float* W2   = (const float*)d_in[4];
    const float* b2   = (const float*)d_in[5];
    const float* Wd   = (const float*)d_in[6];
    const float* bd   = (const float*)d_in[7];
    const void*  edges = d_in[8];
    const void*  perm  = d_in[9];

    float* out    = (float*)d_out;
    float* out_x1 = out;
    float* out_r1 = out + NN * H2D;
    float* out_rc = out + NN * H2D + NN * 2;

    const int SMEM_TC = 2 * STAGEB;          // 81920 B dynamic
    cudaFuncSetAttribute(k_gemm1_tc,
                         cudaFuncAttributeMaxDynamicSharedMemorySize, SMEM_TC);

    k_init0det <<<EE / 256, 256>>>(edges);
    k_convA    <<<NN * (KPAD/8) / 256, 256>>>(gene);
    k_convB    <<<H1D * (KPAD/8) / 256, 256>>>(W1);

    dim3 gg1(H1D / 128, NN / 128);           // (2, 64) = 128 CTAs — launch #4
    k_gemm1_tc <<<gg1, 256, SMEM_TC>>>();

    k_perm_int <<<NN / 256, 256>>>(perm);
    k_deg_count<<<EE / 256, 256>>>(edges);
    k_dinv     <<<NN / 256, 256>>>();
    k_scan     <<<1, 256>>>();
    k_fill     <<<EE / 256, 256>>>(edges);

    k_gather1  <<<NN / 2, 128>>>(b1);
    k_gemm2    <<<128, 256>>>(W2);
    k_gather2  <<<NN / 16, 256>>>(b2, out_x1);

    k_readout  <<<NN, 256>>>(mask, out_x1);
    k_bilinear <<<NN, 64>>>(Wd, bd, out_x1, out_r1, out_rc);
}

// round 13
// speedup vs baseline: 1.5340x; 1.0168x over previous
#include <cuda_runtime.h>
#include <cuda_bf16.h>
#include <math.h>

#define NN   8192
#define EE   131072
#define IND  3000
#define H1D  256
#define H2D  64
#define KPAD 3008            // 94 * 32
#define CH   32              // K per smem stage
#define NST  (KPAD/CH)       // 94
#define SROW 40              // smem row stride in bf16 (80B: conflict-free ldmatrix)
#define MATB (128*SROW*2)    // 10240 B per 128-row matrix
#define STAGEB (4*MATB)      // 40960 B per stage (Ah,Al,Bh,Bl)
#define NSTG 3               // cp.async ring depth

typedef unsigned long long u64;
typedef unsigned u32;

// ---------------- scratch ----------------
__device__ float g_XW   [NN*H1D];
__device__ float g_H1   [NN*H1D];
__device__ float g_H1c  [NN*H1D];
__device__ float g_XW2  [NN*H2D];
__device__ float g_XW2c [NN*H2D];
__device__ float g_X2c  [NN*H2D];
__device__ float g_G1   [NN*H2D];
__device__ float g_G1c  [NN*H2D];
__device__ float g_dinv [NN];
__device__ int   g_deg  [NN];
__device__ int   g_off  [NN+1];
__device__ int   g_fill [NN];
__device__ int   g_permI[NN];
__device__ int   g_csr_src [EE];
__device__ int   g_csr_psrc[EE];
__device__ float g_csr_nm  [EE];
__device__ int   g_notI64;            // zero at load; set deterministically
__device__ __nv_bfloat16 g_Ah[(size_t)NN*KPAD];
__device__ __nv_bfloat16 g_Al[(size_t)NN*KPAD];
__device__ __nv_bfloat16 g_Bh[(size_t)H1D*KPAD];
__device__ __nv_bfloat16 g_Bl[(size_t)H1D*KPAD];

// ---------------- helpers ----------------
__device__ __forceinline__ u64 pack2(float x) {
    u64 r; asm("mov.b64 %0, {%1, %1};" : "=l"(r) : "f"(x)); return r;
}
__device__ __forceinline__ void fma2(u64& d, u64 a, u64 b) {
    asm("fma.rn.f32x2 %0, %1, %2, %0;" : "+l"(d) : "l"(a), "l"(b));
}
__device__ __forceinline__ u32 smem_u32(const void* p) {
    u32 a;
    asm("{ .reg .u64 t; cvta.to.shared.u64 t, %1; cvt.u32.u64 %0, t; }"
        : "=r"(a) : "l"(p));
    return a;
}
__device__ __forceinline__ void ldm_x4(u32* r, u32 addr) {
    asm volatile("ldmatrix.sync.aligned.m8n8.x4.shared.b16 {%0,%1,%2,%3}, [%4];"
                 : "=r"(r[0]), "=r"(r[1]), "=r"(r[2]), "=r"(r[3]) : "r"(addr));
}
__device__ __forceinline__ void mma_bf16(float* d, const u32* a, u32 b0, u32 b1) {
    asm volatile(
        "mma.sync.aligned.m16n8k16.row.col.f32.bf16.bf16.f32 "
        "{%0,%1,%2,%3}, {%4,%5,%6,%7}, {%8,%9}, {%0,%1,%2,%3};"
        : "+f"(d[0]), "+f"(d[1]), "+f"(d[2]), "+f"(d[3])
        : "r"(a[0]), "r"(a[1]), "r"(a[2]), "r"(a[3]), "r"(b0), "r"(b1));
}
__device__ __forceinline__ void cp16(u32 dst, const void* src) {
    asm volatile("cp.async.cg.shared.global [%0], [%1], 16;"
                 :: "r"(dst), "l"(src) : "memory");
}
#define CP_COMMIT() asm volatile("cp.async.commit_group;" ::: "memory")
#define CP_WAIT1()  asm volatile("cp.async.wait_group 1;" ::: "memory")
__device__ __forceinline__ int idx_at(const void* p, int i, int is64) {
    return is64 ? (int)((const long long*)p)[i] : ((const int*)p)[i];
}

// ---------------- setup: deg init + dtype detect --------------------
__global__ void k_init0det(const void* edges) {
    int i = blockIdx.x * blockDim.x + threadIdx.x;   // grid covers EE
    if (i < NN) g_deg[i] = 1;
    const long long* p = (const long long*)edges;
    long long v = p[i];
    if (v < 0 || v >= NN) g_notI64 = 1;
}

// ---------------- bf16 hi/lo split conversions ----------------------
__global__ void k_convA(const float* __restrict__ A) {
    int idx = blockIdx.x * 256 + threadIdx.x;        // NN * (KPAD/8)
    int m = idx / (KPAD/8), g = idx % (KPAD/8);
    int k = g * 8;
    __align__(16) __nv_bfloat16 h[8], l[8];
    if (k < IND) {                                    // 3000/8 = 375 full groups
        const float* p = A + (size_t)m * IND + k;
#pragma unroll
        for (int j = 0; j < 8; j++) {
            float v = p[j];
            __nv_bfloat16 hh = __float2bfloat16(v);
            h[j] = hh;
            l[j] = __float2bfloat16(v - __bfloat162float(hh));
        }
    } else {
#pragma unroll
        for (int j = 0; j < 8; j++) { h[j] = __float2bfloat16(0.f); l[j] = h[j]; }
    }
    *(uint4*)&g_Ah[(size_t)m * KPAD + k] = *(uint4*)h;
    *(uint4*)&g_Al[(size_t)m * KPAD + k] = *(uint4*)l;
}

__global__ void k_convB(const float* __restrict__ W1) {
    int idx = blockIdx.x * 256 + threadIdx.x;        // H1D * (KPAD/8)
    int n = idx / (KPAD/8), g = idx % (KPAD/8);
    int k = g * 8;
    __align__(16) __nv_bfloat16 h[8], l[8];
#pragma unroll
    for (int j = 0; j < 8; j++) {
        int kk = k + j;
        float v = (kk < IND) ? W1[(size_t)kk * H1D + n] : 0.f;
        __nv_bfloat16 hh = __float2bfloat16(v);
        h[j] = hh;
        l[j] = __float2bfloat16(v - __bfloat162float(hh));
    }
    *(uint4*)&g_Bh[(size_t)n * KPAD + k] = *(uint4*)h;
    *(uint4*)&g_Bl[(size_t)n * KPAD + k] = *(uint4*)l;
}

// ---------------- GEMM1 via mma.sync bf16 (3-term split) -----------
// CTA 128x128, 8 warps (warp tile 64x32), 3-stage cp.async ring.
// D = Ah*Bh + Ah*Bl + Al*Bh, fp32 accum.
__global__ void __launch_bounds__(256)
k_gemm1_tc() {
    extern __shared__ char smem[];
    u32 sb = smem_u32(smem);
    int tid = threadIdx.x;
    int wid = tid >> 5, lane = tid & 31;
    int wm = wid & 1, wn = wid >> 1;        // warp grid 2(M) x 4(N)
    int m0 = blockIdx.y * 128;
    int n0 = blockIdx.x * 128;

    // global load descriptors: 8 x 16B per thread per stage
    // idx = q*256+tid: mat = idx/512 (0:Ah 1:Al 2:Bh 3:Bl), r=(idx%512)/4, kq=idx%4
    u32 sdst[8];
    size_t goff[8];
    const __nv_bfloat16* gm[8];
#pragma unroll
    for (int q = 0; q < 8; q++) {
        int idx = q * 256 + tid;
        int mat = idx >> 9, rem = idx & 511;
        int r = rem >> 2, kq = rem & 3;
        sdst[q] = (u32)(mat * MATB + r * (SROW*2) + kq * 16);
        int grow = (mat < 2) ? (m0 + r) : (n0 + r);
        goff[q] = (size_t)grow * KPAD + kq * 8;
        gm[q] = (mat == 0) ? g_Ah : (mat == 1) ? g_Al : (mat == 2) ? g_Bh : g_Bl;
    }

    // ldmatrix lane address bases (byte offsets within a matrix)
    u32 aBase = (u32)((wm*64 + (lane & 15)) * (SROW*2) + (lane >> 4) * 16);
    u32 bBase = (u32)((wn*32 + ((lane >> 4) * 8) + (lane & 7)) * (SROW*2)
                      + ((lane >> 3) & 1) * 16);

    float acc[4][4][4];
#pragma unroll
    for (int i = 0; i < 4; i++)
#pragma unroll
        for (int j = 0; j < 4; j++)
#pragma unroll
            for (int q = 0; q < 4; q++) acc[i][j][q] = 0.f;

    // preload stages 0,1 (group index == stage index)
#pragma unroll
    for (int s = 0; s < 2; s++) {
        size_t ko = (size_t)s * CH;
#pragma unroll
        for (int q = 0; q < 8; q++)
            cp16(sb + s * STAGEB + sdst[q], &gm[q][goff[q] + ko]);
        CP_COMMIT();
    }

    for (int c = 0; c < NST; c++) {
        CP_WAIT1();            // groups 0..c complete -> stage c ready
        __syncthreads();
        u32 bufb = sb + (c % NSTG) * STAGEB;
#pragma unroll
        for (int ks = 0; ks < 2; ks++) {
            u32 ko = ks * 32;                 // 16 bf16 = 32 bytes
            u32 ah[4][4], al[4][4], bh[2][4], bl[2][4];
#pragma unroll
            for (int mt = 0; mt < 4; mt++) {
                u32 ao = bufb + aBase + mt * (16*SROW*2) + ko;
                ldm_x4(ah[mt], ao);
                ldm_x4(al[mt], ao + MATB);
            }
#pragma unroll
            for (int t = 0; t < 2; t++) {
                u32 bo = bufb + 2*MATB + bBase + t * (16*SROW*2) + ko;
                ldm_x4(bh[t], bo);
                ldm_x4(bl[t], bo + MATB);
            }
#pragma unroll
            for (int mt = 0; mt < 4; mt++)
#pragma unroll
                for (int nt = 0; nt < 4; nt++) {
                    int t = nt >> 1, s = (nt & 1) * 2;
                    mma_bf16(acc[mt][nt], ah[mt], bh[t][s], bh[t][s+1]);
                    mma_bf16(acc[mt][nt], ah[mt], bl[t][s], bl[t][s+1]);
                    mma_bf16(acc[mt][nt], al[mt], bh[t][s], bh[t][s+1]);
                }
        }
        // issue stage c+2 into slot (c+2)%3; always commit (group idx == stage)
        if (c + 2 < NST) {
            size_t ko = (size_t)(c + 2) * CH;
            u32 nb = sb + ((c + 2) % NSTG) * STAGEB;
#pragma unroll
            for (int q = 0; q < 8; q++)
                cp16(nb + sdst[q], &gm[q][goff[q] + ko]);
        }
        CP_COMMIT();
        __syncthreads();
    }

    // epilogue: m16n8 accum: c0,c1 -> (lane/4, (lane%4)*2); c2,c3 -> row+8
    int er = lane >> 2, ec = (lane & 3) * 2;
#pragma unroll
    for (int mt = 0; mt < 4; mt++) {
#pragma unroll
        for (int nt = 0; nt < 4; nt++) {
            int row = m0 + wm*64 + mt*16 + er;
            int col = n0 + wn*32 + nt*8 + ec;
            *(float2*)&g_XW[(size_t)row * H1D + col] =
                make_float2(acc[mt][nt][0], acc[mt][nt][1]);
            *(float2*)&g_XW[(size_t)(row + 8) * H1D + col] =
                make_float2(acc[mt][nt][2], acc[mt][nt][3]);
        }
    }
}

// ---------------- graph setup ----------------
__global__ void k_perm_int(const void* permp) {
    int i = blockIdx.x * blockDim.x + threadIdx.x;
    if (i < NN) g_permI[i] = idx_at(permp, i, !g_notI64);
}
__global__ void k_deg_count(const void* edges) {
    int e = blockIdx.x * blockDim.x + threadIdx.x;
    if (e >= EE) return;
    atomicAdd(&g_deg[idx_at(edges, EE + e, !g_notI64)], 1);
}
__global__ void k_dinv() {
    int i = blockIdx.x * blockDim.x + threadIdx.x;
    if (i < NN) g_dinv[i] = rsqrtf((float)g_deg[i]);
}
__global__ void k_scan() {
    __shared__ int partial[256];
    int t = threadIdx.x;
    int base = t * 32;
    int local[32];
    int sum = 0;
#pragma unroll
    for (int j = 0; j < 32; j++) {
        int c = g_deg[base + j] - 1;
        local[j] = sum;
        sum += c;
    }
    partial[t] = sum;
    __syncthreads();
    for (int o = 1; o < 256; o <<= 1) {
        int u = (t >= o) ? partial[t - o] : 0;
        __syncthreads();
        partial[t] += u;
        __syncthreads();
    }
    int off0 = partial[t] - sum;
#pragma unroll
    for (int j = 0; j < 32; j++) {
        int o = off0 + local[j];
        g_off[base + j]  = o;
        g_fill[base + j] = o;
    }
    if (t == 255) g_off[NN] = partial[255];
}
__global__ void k_fill(const void* edges) {
    int e = blockIdx.x * blockDim.x + threadIdx.x;
    if (e >= EE) return;
    int is64 = !g_notI64;
    int s = idx_at(edges, e, is64);
    int d = idx_at(edges, EE + e, is64);
    int pos = atomicAdd(&g_fill[d], 1);
    g_csr_src [pos] = s;
    g_csr_psrc[pos] = g_permI[s];
    g_csr_nm  [pos] = g_dinv[s] * g_dinv[d];
}

// ---------------- conv1 gather ----------------
__global__ void k_gather1(const float* __restrict__ b1) {
    int tid = threadIdx.x;            // 128
    int i = blockIdx.x * 2 + (tid >> 6);
    int l = (tid & 63) * 4;
    float s2 = g_dinv[i] * g_dinv[i];
    int pi = g_permI[i];
    float4 x0 = *(const float4*)&g_XW[(size_t)i  * H1D + l];
    float4 xp = *(const float4*)&g_XW[(size_t)pi * H1D + l];
    float4 acc  = make_float4(s2*x0.x, s2*x0.y, s2*x0.z, s2*x0.w);
    float4 accc = make_float4(s2*xp.x, s2*xp.y, s2*xp.z, s2*xp.w);
    int e1 = g_off[i + 1];
    for (int e = g_off[i]; e < e1; e++) {
        int s  = g_csr_src[e];
        int ps = g_csr_psrc[e];
        float nm = g_csr_nm[e];
        float4 xs = *(const float4*)&g_XW[(size_t)s  * H1D + l];
        float4 xq = *(const float4*)&g_XW[(size_t)ps * H1D + l];
        acc.x  += nm*xs.x; acc.y  += nm*xs.y; acc.z  += nm*xs.z; acc.w  += nm*xs.w;
        accc.x += nm*xq.x; accc.y += nm*xq.y; accc.z += nm*xq.z; accc.w += nm*xq.w;
    }
    float4 bb = *(const float4*)&b1[l];
    float4 v;
    v.x = fmaxf(acc.x + bb.x, 0.f); v.y = fmaxf(acc.y + bb.y, 0.f);
    v.z = fmaxf(acc.z + bb.z, 0.f); v.w = fmaxf(acc.w + bb.w, 0.f);
    *(float4*)&g_H1[(size_t)i * H1D + l] = v;
    v.x = fmaxf(accc.x + bb.x, 0.f); v.y = fmaxf(accc.y + bb.y, 0.f);
    v.z = fmaxf(accc.z + bb.z, 0.f); v.w = fmaxf(accc.w + bb.w, 0.f);
    *(float4*)&g_H1c[(size_t)i * H1D + l] = v;
}

// ---------------- GEMM2: [2*8192,256]@[256,64] ----------------------
__global__ void __launch_bounds__(256, 1)
k_gemm2(const float* __restrict__ W2) {
    const float* Am = (blockIdx.x < 64) ? g_H1  : g_H1c;
    float*       Om = (blockIdx.x < 64) ? g_XW2 : g_XW2c;
    int m0 = (blockIdx.x & 63) * 128;

    __shared__ float As[2][8][128];
    __shared__ float Bs[2][8][64];
    int tid = threadIdx.x;
    int ty = tid >> 4, tx = tid & 15;
    int ar = tid >> 1, ak = (tid & 1) * 4;
    int br = tid >> 5, bc = (tid & 31) * 2;
    const float* Aptr = Am + (size_t)(m0 + ar) * H1D + ak;
    const float* Bptr = W2 + (size_t)br * H2D + bc;

    u64 acc[8][2];
#pragma unroll
    for (int i = 0; i < 8; i++) { acc[i][0] = 0ull; acc[i][1] = 0ull; }

    float4 a0 = *(const float4*)Aptr;
    float2 b0 = *(const float2*)Bptr;
    As[0][ak+0][ar] = a0.x; As[0][ak+1][ar] = a0.y;
    As[0][ak+2][ar] = a0.z; As[0][ak+3][ar] = a0.w;
    *(float2*)&Bs[0][br][bc] = b0;
    __syncthreads();

    int buf = 0;
    for (int k0 = 8; k0 < H1D; k0 += 8) {
        float4 an = *(const float4*)(Aptr + k0);
        float2 bn = *(const float2*)(Bptr + (size_t)k0 * H2D);
#pragma unroll
        for (int kk = 0; kk < 8; kk++) {
            float ra[8];
            *(float4*)&ra[0] = *(const float4*)&As[buf][kk][ty*8];
            *(float4*)&ra[4] = *(const float4*)&As[buf][kk][ty*8+4];
            ulonglong2 rb = *(const ulonglong2*)&Bs[buf][kk][tx*4];
#pragma unroll
            for (int i = 0; i < 8; i++) {
                u64 aa = pack2(ra[i]);
                fma2(acc[i][0], aa, rb.x);
                fma2(acc[i][1], aa, rb.y);
            }
        }
        buf ^= 1;
        As[buf][ak+0][ar] = an.x; As[buf][ak+1][ar] = an.y;
        As[buf][ak+2][ar] = an.z; As[buf][ak+3][ar] = an.w;
        *(float2*)&Bs[buf][br][bc] = bn;
        __syncthreads();
    }
#pragma unroll
    for (int kk = 0; kk < 8; kk++) {
        float ra[8];
        *(float4*)&ra[0] = *(const float4*)&As[buf][kk][ty*8];
        *(float4*)&ra[4] = *(const float4*)&As[buf][kk][ty*8+4];
        ulonglong2 rb = *(const ulonglong2*)&Bs[buf][kk][tx*4];
#pragma unroll
        for (int i = 0; i < 8; i++) {
            u64 aa = pack2(ra[i]);
            fma2(acc[i][0], aa, rb.x);
            fma2(acc[i][1], aa, rb.y);
        }
    }

#pragma unroll
    for (int i = 0; i < 8; i++) {
        ulonglong2 v; v.x = acc[i][0]; v.y = acc[i][1];
        *(ulonglong2*)&Om[(size_t)(m0 + ty*8 + i) * H2D + tx*4] = v;
    }
}

// ---------------- conv2 gather ----------------
__global__ void k_gather2(const float* __restrict__ b2, float* __restrict__ out_x1) {
    int t = threadIdx.x;            // 256
    int i = blockIdx.x * 16 + (t >> 4);
    int l = (t & 15) * 4;
    float s2 = g_dinv[i] * g_dinv[i];
    float4 x0 = *(const float4*)&g_XW2 [(size_t)i * H2D + l];
    float4 xc = *(const float4*)&g_XW2c[(size_t)i * H2D + l];
    float4 acc  = make_float4(s2*x0.x, s2*x0.y, s2*x0.z, s2*x0.w);
    float4 accc = make_float4(s2*xc.x, s2*xc.y, s2*xc.z, s2*xc.w);
    int e1 = g_off[i + 1];
    for (int e = g_off[i]; e < e1; e++) {
        int s = g_csr_src[e];
        float nm = g_csr_nm[e];
        float4 xs = *(const float4*)&g_XW2 [(size_t)s * H2D + l];
        float4 xq = *(const float4*)&g_XW2c[(size_t)s * H2D + l];
        acc.x  += nm*xs.x; acc.y  += nm*xs.y; acc.z  += nm*xs.z; acc.w  += nm*xs.w;
        accc.x += nm*xq.x; accc.y += nm*xq.y; accc.z += nm*xq.z; accc.w += nm*xq.w;
    }
    float4 bb = *(const float4*)&b2[l];
    float4 v;
    v.x = fmaxf(acc.x + bb.x, 0.f); v.y = fmaxf(acc.y + bb.y, 0.f);
    v.z = fmaxf(acc.z + bb.z, 0.f); v.w = fmaxf(acc.w + bb.w, 0.f);
    *(float4*)&out_x1[(size_t)i * H2D + l] = v;
    v.x = fmaxf(accc.x + bb.x, 0.f); v.y = fmaxf(accc.y + bb.y, 0.f);
    v.z = fmaxf(accc.z + bb.z, 0.f); v.w = fmaxf(accc.w + bb.w, 0.f);
    *(float4*)&g_X2c[(size_t)i * H2D + l] = v;
}

// ---------------- readout ----------------
__global__ void k_readout(const float* __restrict__ mask, const float* __restrict__ x1) {
    __shared__ int   s_idx[1024];
    __shared__ float s_val[1024];
    __shared__ int   s_cnt;
    __shared__ float s_rs;
    __shared__ float part1[4][H2D], part2[4][H2D];
    __shared__ float vs1[H2D], vs2[H2D];
    __shared__ float nrm1, nrm2;
    int i = blockIdx.x;
    int tid = threadIdx.x;  // 256
    if (tid == 0) { s_cnt = 0; s_rs = 0.f; }
    __syncthreads();

    float rs = 0.f;
    const float4* m4 = (const float4*)&mask[(size_t)i * NN];
    for (int j4 = tid; j4 < NN / 4; j4 += 256) {
        float4 m = m4[j4];
        rs += m.x + m.y + m.z + m.w;
        if (m.x != 0.f) { int p = atomicAdd(&s_cnt, 1); if (p < 1024) { s_idx[p] = j4*4;   s_val[p] = m.x; } }
        if (m.y != 0.f) { int p = atomicAdd(&s_cnt, 1); if (p < 1024) { s_idx[p] = j4*4+1; s_val[p] = m.y; } }
        if (m.z != 0.f) { int p = atomicAdd(&s_cnt, 1); if (p < 1024) { s_idx[p] = j4*4+2; s_val[p] = m.z; } }
        if (m.w != 0.f) { int p = atomicAdd(&s_cnt, 1); if (p < 1024) { s_idx[p] = j4*4+3; s_val[p] = m.w; } }
    }
#pragma unroll
    for (int o = 16; o; o >>= 1) rs += __shfl_down_sync(0xFFFFFFFFu, rs, o);
    if ((tid & 31) == 0) atomicAdd(&s_rs, rs);
    __syncthreads();

    int cnt = s_cnt < 1024 ? s_cnt : 1024;
    int g = tid >> 6, f = tid & 63;
    float a1 = 0.f, a2 = 0.f;
    for (int e = g; e < cnt; e += 4) {
        int j = s_idx[e];
        float mv = s_val[e];
        a1 += mv * x1   [(size_t)j * H2D + f];
        a2 += mv * g_X2c[(size_t)j * H2D + f];
    }
    part1[g][f] = a1;
    part2[g][f] = a2;
    __syncthreads();

    if (tid < H2D) {
        float inv = 1.0f / s_rs;
        vs1[tid] = (part1[0][tid] + part1[1][tid] + part1[2][tid] + part1[3][tid]) * inv;
        vs2[tid] = (part2[0][tid] + part2[1][tid] + part2[2][tid] + part2[3][tid]) * inv;
    }
    __syncthreads();
    if (tid == 0) {
        float s1 = 0.f, s2 = 0.f;
        for (int q = 0; q < H2D; q++) { s1 += vs1[q]*vs1[q]; s2 += vs2[q]*vs2[q]; }
        nrm1 = fmaxf(sqrtf(s1), 1e-12f);
        nrm2 = fmaxf(sqrtf(s2), 1e-12f);
    }
    __syncthreads();
    if (tid < H2D) {
        float v1 = vs1[tid] / nrm1;
        float v2 = vs2[tid] / nrm2;
        g_G1 [i*H2D + tid] = 1.0f / (1.0f + expf(-v1));
        g_G1c[i*H2D + tid] = 1.0f / (1.0f + expf(-v2));
    }
}

// ---------------- bilinear ----------------
__global__ void k_bilinear(const float* __restrict__ Wd, const float* __restrict__ bd,
                           const float* __restrict__ x1,
                           float* __restrict__ ret1, float* __restrict__ ret1c) {
    __shared__ float c1[H2D], c2[H2D], h[H2D], hc[H2D];
    __shared__ float red[4][H2D];
    int i = blockIdx.x;
    int k = threadIdx.x;  // 64
    c1[k] = g_G1 [i*H2D + k];
    c2[k] = g_G1c[i*H2D + k];
    h [k] = x1   [(size_t)i*H2D + k];
    hc[k] = g_X2c[(size_t)i*H2D + k];
    __syncthreads();
    float t1 = 0.f, t2 = 0.f;
    const float4* wr = (const float4*)&Wd[k * H2D];
#pragma unroll
    for (int j4 = 0; j4 < H2D / 4; j4++) {
        float4 w = wr[j4];
        t1 += w.x*c1[j4*4] + w.y*c1[j4*4+1] + w.z*c1[j4*4+2] + w.w*c1[j4*4+3];
        t2 += w.x*c2[j4*4] + w.y*c2[j4*4+1] + w.z*c2[j4*4+2] + w.w*c2[j4*4+3];
    }
    red[0][k] = h [k] * t1;
    red[1][k] = hc[k] * t1;
    red[2][k] = hc[k] * t2;
    red[3][k] = h [k] * t2;
    __syncthreads();
    if (k < 4) {
        float s = 0.f;
        for (int j = 0; j < H2D; j++) s += red[k][j];
        s += bd[0];
        if (k == 0) ret1 [i*2 + 0] = s;
        if (k == 1) ret1 [i*2 + 1] = s;
        if (k == 2) ret1c[i*2 + 0] = s;
        if (k == 3) ret1c[i*2 + 1] = s;
    }
}

// ---------------- launch ----------------
extern "C" void kernel_launch(void* const* d_in, const int* in_sizes, int n_in,
                              void* d_out, int out_size) {
    const float* gene = (const float*)d_in[0];
    const float* mask = (const float*)d_in[1];
    const float* W1   = (const float*)d_in[2];
    const float* b1   = (const float*)d_in[3];
    const float* W2   = (const float*)d_in[4];
    const float* b2   = (const float*)d_in[5];
    const float* Wd   = (const float*)d_in[6];
    const float* bd   = (const float*)d_in[7];
    const void*  edges = d_in[8];
    const void*  perm  = d_in[9];

    float* out    = (float*)d_out;
    float* out_x1 = out;
    float* out_r1 = out + NN * H2D;
    float* out_rc = out + NN * H2D + NN * 2;

    const int SMEM_TC = NSTG * STAGEB;       // 122880 B dynamic
    cudaFuncSetAttribute(k_gemm1_tc,
                         cudaFuncAttributeMaxDynamicSharedMemorySize, SMEM_TC);

    k_init0det <<<EE / 256, 256>>>(edges);
    k_convA    <<<NN * (KPAD/8) / 256, 256>>>(gene);
    k_convB    <<<H1D * (KPAD/8) / 256, 256>>>(W1);

    dim3 gg1(H1D / 128, NN / 128);           // (2, 64) = 128 CTAs — launch #4
    k_gemm1_tc <<<gg1, 256, SMEM_TC>>>();

    k_perm_int <<<NN / 256, 256>>>(perm);
    k_deg_count<<<EE / 256, 256>>>(edges);
    k_dinv     <<<NN / 256, 256>>>();
    k_scan     <<<1, 256>>>();
    k_fill     <<<EE / 256, 256>>>(edges);

    k_gather1  <<<NN / 2, 128>>>(b1);
    k_gemm2    <<<128, 256>>>(W2);
    k_gather2  <<<NN / 16, 256>>>(b2, out_x1);

    k_readout  <<<NN, 256>>>(mask, out_x1);
    k_bilinear <<<NN, 64>>>(Wd, bd, out_x1, out_r1, out_rc);
}

// round 14
// speedup vs baseline: 1.5430x; 1.0059x over previous
#include <cuda_runtime.h>
#include <cuda_bf16.h>
#include <math.h>

#define NN   8192
#define EE   131072
#define IND  3000
#define H1D  256
#define H2D  64
#define KPAD 3008            // 94 * 32
#define CH   32              // K per smem stage
#define NST  (KPAD/CH)       // 94
#define SROW 40              // smem row stride in bf16 (80B: conflict-free ldmatrix)
// CTA tile 64(M) x 128(N); per stage: Ah,Al 64 rows + Bh,Bl 128 rows
#define OFF_AH 0
#define OFF_AL 5120          // 64*80
#define OFF_BH 10240
#define OFF_BL 20480         // 10240 + 128*80
#define STAGEB 30720
#define NSTG 3               // cp.async ring depth (92160 B; 2 CTAs/SM fit)

typedef unsigned long long u64;
typedef unsigned u32;

// ---------------- scratch ----------------
__device__ float g_XW   [NN*H1D];
__device__ float g_H1   [NN*H1D];
__device__ float g_H1c  [NN*H1D];
__device__ float g_XW2  [NN*H2D];
__device__ float g_XW2c [NN*H2D];
__device__ float g_X2c  [NN*H2D];
__device__ float g_G1   [NN*H2D];
__device__ float g_G1c  [NN*H2D];
__device__ float g_dinv [NN];
__device__ int   g_deg  [NN];
__device__ int   g_off  [NN+1];
__device__ int   g_fill [NN];
__device__ int   g_permI[NN];
__device__ int   g_csr_src [EE];
__device__ int   g_csr_psrc[EE];
__device__ float g_csr_nm  [EE];
__device__ int   g_notI64;            // zero at load; set deterministically
__device__ __nv_bfloat16 g_Ah[(size_t)NN*KPAD];
__device__ __nv_bfloat16 g_Al[(size_t)NN*KPAD];
__device__ __nv_bfloat16 g_Bh[(size_t)H1D*KPAD];
__device__ __nv_bfloat16 g_Bl[(size_t)H1D*KPAD];

// ---------------- helpers ----------------
__device__ __forceinline__ u64 pack2(float x) {
    u64 r; asm("mov.b64 %0, {%1, %1};" : "=l"(r) : "f"(x)); return r;
}
__device__ __forceinline__ void fma2(u64& d, u64 a, u64 b) {
    asm("fma.rn.f32x2 %0, %1, %2, %0;" : "+l"(d) : "l"(a), "l"(b));
}
__device__ __forceinline__ u32 smem_u32(const void* p) {
    u32 a;
    asm("{ .reg .u64 t; cvta.to.shared.u64 t, %1; cvt.u32.u64 %0, t; }"
        : "=r"(a) : "l"(p));
    return a;
}
__device__ __forceinline__ void ldm_x4(u32* r, u32 addr) {
    asm volatile("ldmatrix.sync.aligned.m8n8.x4.shared.b16 {%0,%1,%2,%3}, [%4];"
                 : "=r"(r[0]), "=r"(r[1]), "=r"(r[2]), "=r"(r[3]) : "r"(addr));
}
__device__ __forceinline__ void mma_bf16(float* d, const u32* a, u32 b0, u32 b1) {
    asm volatile(
        "mma.sync.aligned.m16n8k16.row.col.f32.bf16.bf16.f32 "
        "{%0,%1,%2,%3}, {%4,%5,%6,%7}, {%8,%9}, {%0,%1,%2,%3};"
        : "+f"(d[0]), "+f"(d[1]), "+f"(d[2]), "+f"(d[3])
        : "r"(a[0]), "r"(a[1]), "r"(a[2]), "r"(a[3]), "r"(b0), "r"(b1));
}
__device__ __forceinline__ void cp16(u32 dst, const void* src) {
    asm volatile("cp.async.cg.shared.global [%0], [%1], 16;"
                 :: "r"(dst), "l"(src) : "memory");
}
#define CP_COMMIT() asm volatile("cp.async.commit_group;" ::: "memory")
#define CP_WAIT1()  asm volatile("cp.async.wait_group 1;" ::: "memory")
__device__ __forceinline__ int idx_at(const void* p, int i, int is64) {
    return is64 ? (int)((const long long*)p)[i] : ((const int*)p)[i];
}

// ---------------- setup: deg init + dtype detect --------------------
__global__ void k_init0det(const void* edges) {
    int i = blockIdx.x * blockDim.x + threadIdx.x;   // grid covers EE
    if (i < NN) g_deg[i] = 1;
    const long long* p = (const long long*)edges;
    long long v = p[i];
    if (v < 0 || v >= NN) g_notI64 = 1;
}

// ---------------- bf16 hi/lo split conversions ----------------------
__global__ void k_convA(const float* __restrict__ A) {
    int idx = blockIdx.x * 256 + threadIdx.x;        // NN * (KPAD/8)
    int m = idx / (KPAD/8), g = idx % (KPAD/8);
    int k = g * 8;
    __align__(16) __nv_bfloat16 h[8], l[8];
    if (k < IND) {                                    // 3000/8 = 375 full groups
        const float* p = A + (size_t)m * IND + k;
#pragma unroll
        for (int j = 0; j < 8; j++) {
            float v = p[j];
            __nv_bfloat16 hh = __float2bfloat16(v);
            h[j] = hh;
            l[j] = __float2bfloat16(v - __bfloat162float(hh));
        }
    } else {
#pragma unroll
        for (int j = 0; j < 8; j++) { h[j] = __float2bfloat16(0.f); l[j] = h[j]; }
    }
    *(uint4*)&g_Ah[(size_t)m * KPAD + k] = *(uint4*)h;
    *(uint4*)&g_Al[(size_t)m * KPAD + k] = *(uint4*)l;
}

__global__ void k_convB(const float* __restrict__ W1) {
    int idx = blockIdx.x * 256 + threadIdx.x;        // H1D * (KPAD/8)
    int n = idx / (KPAD/8), g = idx % (KPAD/8);
    int k = g * 8;
    __align__(16) __nv_bfloat16 h[8], l[8];
#pragma unroll
    for (int j = 0; j < 8; j++) {
        int kk = k + j;
        float v = (kk < IND) ? W1[(size_t)kk * H1D + n] : 0.f;
        __nv_bfloat16 hh = __float2bfloat16(v);
        h[j] = hh;
        l[j] = __float2bfloat16(v - __bfloat162float(hh));
    }
    *(uint4*)&g_Bh[(size_t)n * KPAD + k] = *(uint4*)h;
    *(uint4*)&g_Bl[(size_t)n * KPAD + k] = *(uint4*)l;
}

// ---------------- GEMM1 via mma.sync bf16 (3-term split) -----------
// CTA 64x128, 8 warps (warp tile 32x32), 3-stage cp.async ring,
// 256 CTAs -> 2 CTAs/SM. Term-major MMA order breaks RAW chains.
__global__ void __launch_bounds__(256, 2)
k_gemm1_tc() {
    extern __shared__ char smem[];
    u32 sb = smem_u32(smem);
    int tid = threadIdx.x;
    int wid = tid >> 5, lane = tid & 31;
    int wm = wid & 1, wn = wid >> 1;        // warp grid 2(M) x 4(N)
    int m0 = blockIdx.y * 64;
    int n0 = blockIdx.x * 128;

    // global load descriptors: 6 x 16B per thread per stage (1536 chunks)
    u32 sdst[6];
    size_t goff[6];
    const __nv_bfloat16* gm[6];
#pragma unroll
    for (int q = 0; q < 6; q++) {
        int idx = q * 256 + tid;
        int matoff, chunk, grow;
        if (idx < 512) {                   // A: 64 rows x 4 chunks x 2 mats
            matoff = (idx < 256) ? OFF_AH : OFF_AL;
            gm[q]  = (idx < 256) ? g_Ah : g_Al;
            chunk  = idx & 255;
            grow   = m0 + (chunk >> 2);
        } else {                           // B: 128 rows x 4 chunks x 2 mats
            int r2 = idx - 512;
            matoff = (r2 < 512) ? OFF_BH : OFF_BL;
            gm[q]  = (r2 < 512) ? g_Bh : g_Bl;
            chunk  = r2 & 511;
            grow   = n0 + (chunk >> 2);
        }
        sdst[q] = (u32)(matoff + (chunk >> 2) * (SROW*2) + (chunk & 3) * 16);
        goff[q] = (size_t)grow * KPAD + (chunk & 3) * 8;
    }

    // ldmatrix lane address bases (byte offsets within the stage)
    u32 aBase = (u32)((wm*32 + (lane & 15)) * (SROW*2) + (lane >> 4) * 16);
    u32 bBase = (u32)((wn*32 + ((lane >> 4) * 8) + (lane & 7)) * (SROW*2)
                      + ((lane >> 3) & 1) * 16);

    float acc[2][4][4];
#pragma unroll
    for (int i = 0; i < 2; i++)
#pragma unroll
        for (int j = 0; j < 4; j++)
#pragma unroll
            for (int q = 0; q < 4; q++) acc[i][j][q] = 0.f;

    // preload stages 0,1 (group index == stage index)
#pragma unroll
    for (int s = 0; s < 2; s++) {
        size_t ko = (size_t)s * CH;
#pragma unroll
        for (int q = 0; q < 6; q++)
            cp16(sb + s * STAGEB + sdst[q], &gm[q][goff[q] + ko]);
        CP_COMMIT();
    }

    for (int c = 0; c < NST; c++) {
        CP_WAIT1();            // groups 0..c complete -> stage c ready
        __syncthreads();
        u32 bufb = sb + (c % NSTG) * STAGEB;
#pragma unroll
        for (int ks = 0; ks < 2; ks++) {
            u32 ko = ks * 32;                 // 16 bf16 = 32 bytes
            u32 ah[2][4], al[2][4], bh[2][4], bl[2][4];
#pragma unroll
            for (int mt = 0; mt < 2; mt++) {
                u32 ao = bufb + aBase + mt * (16*SROW*2) + ko;
                ldm_x4(ah[mt], ao);
                ldm_x4(al[mt], ao + (OFF_AL - OFF_AH));
            }
#pragma unroll
            for (int t = 0; t < 2; t++) {
                u32 bo = bufb + OFF_BH + bBase + t * (16*SROW*2) + ko;
                ldm_x4(bh[t], bo);
                ldm_x4(bl[t], bo + (OFF_BL - OFF_BH));
            }
            // term-major: consecutive writes to same acc are 8 MMAs apart
#pragma unroll
            for (int mt = 0; mt < 2; mt++)
#pragma unroll
                for (int nt = 0; nt < 4; nt++)
                    mma_bf16(acc[mt][nt], ah[mt], bh[nt>>1][(nt&1)*2], bh[nt>>1][(nt&1)*2+1]);
#pragma unroll
            for (int mt = 0; mt < 2; mt++)
#pragma unroll
                for (int nt = 0; nt < 4; nt++)
                    mma_bf16(acc[mt][nt], ah[mt], bl[nt>>1][(nt&1)*2], bl[nt>>1][(nt&1)*2+1]);
#pragma unroll
            for (int mt = 0; mt < 2; mt++)
#pragma unroll
                for (int nt = 0; nt < 4; nt++)
                    mma_bf16(acc[mt][nt], al[mt], bh[nt>>1][(nt&1)*2], bh[nt>>1][(nt&1)*2+1]);
        }
        // issue stage c+2 into slot (c+2)%3; always commit (group idx == stage)
        if (c + 2 < NST) {
            size_t ko = (size_t)(c + 2) * CH;
            u32 nb = sb + ((c + 2) % NSTG) * STAGEB;
#pragma unroll
            for (int q = 0; q < 6; q++)
                cp16(nb + sdst[q], &gm[q][goff[q] + ko]);
        }
        CP_COMMIT();
        __syncthreads();
    }

    // epilogue: m16n8 accum: c0,c1 -> (lane/4, (lane%4)*2); c2,c3 -> row+8
    int er = lane >> 2, ec = (lane & 3) * 2;
#pragma unroll
    for (int mt = 0; mt < 2; mt++) {
#pragma unroll
        for (int nt = 0; nt < 4; nt++) {
            int row = m0 + wm*32 + mt*16 + er;
            int col = n0 + wn*32 + nt*8 + ec;
            *(float2*)&g_XW[(size_t)row * H1D + col] =
                make_float2(acc[mt][nt][0], acc[mt][nt][1]);
            *(float2*)&g_XW[(size_t)(row + 8) * H1D + col] =
                make_float2(acc[mt][nt][2], acc[mt][nt][3]);
        }
    }
}

// ---------------- graph setup ----------------
__global__ void k_perm_int(const void* permp) {
    int i = blockIdx.x * blockDim.x + threadIdx.x;
    if (i < NN) g_permI[i] = idx_at(permp, i, !g_notI64);
}
__global__ void k_deg_count(const void* edges) {
    int e = blockIdx.x * blockDim.x + threadIdx.x;
    if (e >= EE) return;
    atomicAdd(&g_deg[idx_at(edges, EE + e, !g_notI64)], 1);
}
__global__ void k_dinv() {
    int i = blockIdx.x * blockDim.x + threadIdx.x;
    if (i < NN) g_dinv[i] = rsqrtf((float)g_deg[i]);
}
__global__ void k_scan() {
    __shared__ int partial[256];
    int t = threadIdx.x;
    int base = t * 32;
    int local[32];
    int sum = 0;
#pragma unroll
    for (int j = 0; j < 32; j++) {
        int c = g_deg[base + j] - 1;
        local[j] = sum;
        sum += c;
    }
    partial[t] = sum;
    __syncthreads();
    for (int o = 1; o < 256; o <<= 1) {
        int u = (t >= o) ? partial[t - o] : 0;
        __syncthreads();
        partial[t] += u;
        __syncthreads();
    }
    int off0 = partial[t] - sum;
#pragma unroll
    for (int j = 0; j < 32; j++) {
        int o = off0 + local[j];
        g_off[base + j]  = o;
        g_fill[base + j] = o;
    }
    if (t == 255) g_off[NN] = partial[255];
}
__global__ void k_fill(const void* edges) {
    int e = blockIdx.x * blockDim.x + threadIdx.x;
    if (e >= EE) return;
    int is64 = !g_notI64;
    int s = idx_at(edges, e, is64);
    int d = idx_at(edges, EE + e, is64);
    int pos = atomicAdd(&g_fill[d], 1);
    g_csr_src [pos] = s;
    g_csr_psrc[pos] = g_permI[s];
    g_csr_nm  [pos] = g_dinv[s] * g_dinv[d];
}

// ---------------- conv1 gather ----------------
__global__ void k_gather1(const float* __restrict__ b1) {
    int tid = threadIdx.x;            // 128
    int i = blockIdx.x * 2 + (tid >> 6);
    int l = (tid & 63) * 4;
    float s2 = g_dinv[i] * g_dinv[i];
    int pi = g_permI[i];
    float4 x0 = *(const float4*)&g_XW[(size_t)i  * H1D + l];
    float4 xp = *(const float4*)&g_XW[(size_t)pi * H1D + l];
    float4 acc  = make_float4(s2*x0.x, s2*x0.y, s2*x0.z, s2*x0.w);
    float4 accc = make_float4(s2*xp.x, s2*xp.y, s2*xp.z, s2*xp.w);
    int e1 = g_off[i + 1];
    for (int e = g_off[i]; e < e1; e++) {
        int s  = g_csr_src[e];
        int ps = g_csr_psrc[e];
        float nm = g_csr_nm[e];
        float4 xs = *(const float4*)&g_XW[(size_t)s  * H1D + l];
        float4 xq = *(const float4*)&g_XW[(size_t)ps * H1D + l];
        acc.x  += nm*xs.x; acc.y  += nm*xs.y; acc.z  += nm*xs.z; acc.w  += nm*xs.w;
        accc.x += nm*xq.x; accc.y += nm*xq.y; accc.z += nm*xq.z; accc.w += nm*xq.w;
    }
    float4 bb = *(const float4*)&b1[l];
    float4 v;
    v.x = fmaxf(acc.x + bb.x, 0.f); v.y = fmaxf(acc.y + bb.y, 0.f);
    v.z = fmaxf(acc.z + bb.z, 0.f); v.w = fmaxf(acc.w + bb.w, 0.f);
    *(float4*)&g_H1[(size_t)i * H1D + l] = v;
    v.x = fmaxf(accc.x + bb.x, 0.f); v.y = fmaxf(accc.y + bb.y, 0.f);
    v.z = fmaxf(accc.z + bb.z, 0.f); v.w = fmaxf(accc.w + bb.w, 0.f);
    *(float4*)&g_H1c[(size_t)i * H1D + l] = v;
}

// ---------------- GEMM2: [2*8192,256]@[256,64] ----------------------
__global__ void __launch_bounds__(256, 1)
k_gemm2(const float* __restrict__ W2) {
    const float* Am = (blockIdx.x < 64) ? g_H1  : g_H1c;
    float*       Om = (blockIdx.x < 64) ? g_XW2 : g_XW2c;
    int m0 = (blockIdx.x & 63) * 128;

    __shared__ float As[2][8][128];
    __shared__ float Bs[2][8][64];
    int tid = threadIdx.x;
    int ty = tid >> 4, tx = tid & 15;
    int ar = tid >> 1, ak = (tid & 1) * 4;
    int br = tid >> 5, bc = (tid & 31) * 2;
    const float* Aptr = Am + (size_t)(m0 + ar) * H1D + ak;
    const float* Bptr = W2 + (size_t)br * H2D + bc;

    u64 acc[8][2];
#pragma unroll
    for (int i = 0; i < 8; i++) { acc[i][0] = 0ull; acc[i][1] = 0ull; }

    float4 a0 = *(const float4*)Aptr;
    float2 b0 = *(const float2*)Bptr;
    As[0][ak+0][ar] = a0.x; As[0][ak+1][ar] = a0.y;
    As[0][ak+2][ar] = a0.z; As[0][ak+3][ar] = a0.w;
    *(float2*)&Bs[0][br][bc] = b0;
    __syncthreads();

    int buf = 0;
    for (int k0 = 8; k0 < H1D; k0 += 8) {
        float4 an = *(const float4*)(Aptr + k0);
        float2 bn = *(const float2*)(Bptr + (size_t)k0 * H2D);
#pragma unroll
        for (int kk = 0; kk < 8; kk++) {
            float ra[8];
            *(float4*)&ra[0] = *(const float4*)&As[buf][kk][ty*8];
            *(float4*)&ra[4] = *(const float4*)&As[buf][kk][ty*8+4];
            ulonglong2 rb = *(const ulonglong2*)&Bs[buf][kk][tx*4];
#pragma unroll
            for (int i = 0; i < 8; i++) {
                u64 aa = pack2(ra[i]);
                fma2(acc[i][0], aa, rb.x);
                fma2(acc[i][1], aa, rb.y);
            }
        }
        buf ^= 1;
        As[buf][ak+0][ar] = an.x; As[buf][ak+1][ar] = an.y;
        As[buf][ak+2][ar] = an.z; As[buf][ak+3][ar] = an.w;
        *(float2*)&Bs[buf][br][bc] = bn;
        __syncthreads();
    }
#pragma unroll
    for (int kk = 0; kk < 8; kk++) {
        float ra[8];
        *(float4*)&ra[0] = *(const float4*)&As[buf][kk][ty*8];
        *(float4*)&ra[4] = *(const float4*)&As[buf][kk][ty*8+4];
        ulonglong2 rb = *(const ulonglong2*)&Bs[buf][kk][tx*4];
#pragma unroll
        for (int i = 0; i < 8; i++) {
            u64 aa = pack2(ra[i]);
            fma2(acc[i][0], aa, rb.x);
            fma2(acc[i][1], aa, rb.y);
        }
    }

#pragma unroll
    for (int i = 0; i < 8; i++) {
        ulonglong2 v; v.x = acc[i][0]; v.y = acc[i][1];
        *(ulonglong2*)&Om[(size_t)(m0 + ty*8 + i) * H2D + tx*4] = v;
    }
}

// ---------------- conv2 gather ----------------
__global__ void k_gather2(const float* __restrict__ b2, float* __restrict__ out_x1) {
    int t = threadIdx.x;            // 256
    int i = blockIdx.x * 16 + (t >> 4);
    int l = (t & 15) * 4;
    float s2 = g_dinv[i] * g_dinv[i];
    float4 x0 = *(const float4*)&g_XW2 [(size_t)i * H2D + l];
    float4 xc = *(const float4*)&g_XW2c[(size_t)i * H2D + l];
    float4 acc  = make_float4(s2*x0.x, s2*x0.y, s2*x0.z, s2*x0.w);
    float4 accc = make_float4(s2*xc.x, s2*xc.y, s2*xc.z, s2*xc.w);
    int e1 = g_off[i + 1];
    for (int e = g_off[i]; e < e1; e++) {
        int s = g_csr_src[e];
        float nm = g_csr_nm[e];
        float4 xs = *(const float4*)&g_XW2 [(size_t)s * H2D + l];
        float4 xq = *(const float4*)&g_XW2c[(size_t)s * H2D + l];
        acc.x  += nm*xs.x; acc.y  += nm*xs.y; acc.z  += nm*xs.z; acc.w  += nm*xs.w;
        accc.x += nm*xq.x; accc.y += nm*xq.y; accc.z += nm*xq.z; accc.w += nm*xq.w;
    }
    float4 bb = *(const float4*)&b2[l];
    float4 v;
    v.x = fmaxf(acc.x + bb.x, 0.f); v.y = fmaxf(acc.y + bb.y, 0.f);
    v.z = fmaxf(acc.z + bb.z, 0.f); v.w = fmaxf(acc.w + bb.w, 0.f);
    *(float4*)&out_x1[(size_t)i * H2D + l] = v;
    v.x = fmaxf(accc.x + bb.x, 0.f); v.y = fmaxf(accc.y + bb.y, 0.f);
    v.z = fmaxf(accc.z + bb.z, 0.f); v.w = fmaxf(accc.w + bb.w, 0.f);
    *(float4*)&g_X2c[(size_t)i * H2D + l] = v;
}

// ---------------- readout ----------------
__global__ void k_readout(const float* __restrict__ mask, const float* __restrict__ x1) {
    __shared__ int   s_idx[1024];
    __shared__ float s_val[1024];
    __shared__ int   s_cnt;
    __shared__ float s_rs;
    __shared__ float part1[4][H2D], part2[4][H2D];
    __shared__ float vs1[H2D], vs2[H2D];
    __shared__ float nrm1, nrm2;
    int i = blockIdx.x;
    int tid = threadIdx.x;  // 256
    if (tid == 0) { s_cnt = 0; s_rs = 0.f; }
    __syncthreads();

    float rs = 0.f;
    const float4* m4 = (const float4*)&mask[(size_t)i * NN];
    for (int j4 = tid; j4 < NN / 4; j4 += 256) {
        float4 m = m4[j4];
        rs += m.x + m.y + m.z + m.w;
        if (m.x != 0.f) { int p = atomicAdd(&s_cnt, 1); if (p < 1024) { s_idx[p] = j4*4;   s_val[p] = m.x; } }
        if (m.y != 0.f) { int p = atomicAdd(&s_cnt, 1); if (p < 1024) { s_idx[p] = j4*4+1; s_val[p] = m.y; } }
        if (m.z != 0.f) { int p = atomicAdd(&s_cnt, 1); if (p < 1024) { s_idx[p] = j4*4+2; s_val[p] = m.z; } }
        if (m.w != 0.f) { int p = atomicAdd(&s_cnt, 1); if (p < 1024) { s_idx[p] = j4*4+3; s_val[p] = m.w; } }
    }
#pragma unroll
    for (int o = 16; o; o >>= 1) rs += __shfl_down_sync(0xFFFFFFFFu, rs, o);
    if ((tid & 31) == 0) atomicAdd(&s_rs, rs);
    __syncthreads();

    int cnt = s_cnt < 1024 ? s_cnt : 1024;
    int g = tid >> 6, f = tid & 63;
    float a1 = 0.f, a2 = 0.f;
    for (int e = g; e < cnt; e += 4) {
        int j = s_idx[e];
        float mv = s_val[e];
        a1 += mv * x1   [(size_t)j * H2D + f];
        a2 += mv * g_X2c[(size_t)j * H2D + f];
    }
    part1[g][f] = a1;
    part2[g][f] = a2;
    __syncthreads();

    if (tid < H2D) {
        float inv = 1.0f / s_rs;
        vs1[tid] = (part1[0][tid] + part1[1][tid] + part1[2][tid] + part1[3][tid]) * inv;
        vs2[tid] = (part2[0][tid] + part2[1][tid] + part2[2][tid] + part2[3][tid]) * inv;
    }
    __syncthreads();
    if (tid == 0) {
        float s1 = 0.f, s2 = 0.f;
        for (int q = 0; q < H2D; q++) { s1 += vs1[q]*vs1[q]; s2 += vs2[q]*vs2[q]; }
        nrm1 = fmaxf(sqrtf(s1), 1e-12f);
        nrm2 = fmaxf(sqrtf(s2), 1e-12f);
    }
    __syncthreads();
    if (tid < H2D) {
        float v1 = vs1[tid] / nrm1;
        float v2 = vs2[tid] / nrm2;
        g_G1 [i*H2D + tid] = 1.0f / (1.0f + expf(-v1));
        g_G1c[i*H2D + tid] = 1.0f / (1.0f + expf(-v2));
    }
}

// ---------------- bilinear ----------------
__global__ void k_bilinear(const float* __restrict__ Wd, const float* __restrict__ bd,
                           const float* __restrict__ x1,
                           float* __restrict__ ret1, float* __restrict__ ret1c) {
    __shared__ float c1[H2D], c2[H2D], h[H2D], hc[H2D];
    __shared__ float red[4][H2D];
    int i = blockIdx.x;
    int k = threadIdx.x;  // 64
    c1[k] = g_G1 [i*H2D + k];
    c2[k] = g_G1c[i*H2D + k];
    h [k] = x1   [(size_t)i*H2D + k];
    hc[k] = g_X2c[(size_t)i*H2D + k];
    __syncthreads();
    float t1 = 0.f, t2 = 0.f;
    const float4* wr = (const float4*)&Wd[k * H2D];
#pragma unroll
    for (int j4 = 0; j4 < H2D / 4; j4++) {
        float4 w = wr[j4];
        t1 += w.x*c1[j4*4] + w.y*c1[j4*4+1] + w.z*c1[j4*4+2] + w.w*c1[j4*4+3];
        t2 += w.x*c2[j4*4] + w.y*c2[j4*4+1] + w.z*c2[j4*4+2] + w.w*c2[j4*4+3];
    }
    red[0][k] = h [k] * t1;
    red[1][k] = hc[k] * t1;
    red[2][k] = hc[k] * t2;
    red[3][k] = h [k] * t2;
    __syncthreads();
    if (k < 4) {
        float s = 0.f;
        for (int j = 0; j < H2D; j++) s += red[k][j];
        s += bd[0];
        if (k == 0) ret1 [i*2 + 0] = s;
        if (k == 1) ret1 [i*2 + 1] = s;
        if (k == 2) ret1c[i*2 + 0] = s;
        if (k == 3) ret1c[i*2 + 1] = s;
    }
}

// ---------------- launch ----------------
extern "C" void kernel_launch(void* const* d_in, const int* in_sizes, int n_in,
                              void* d_out, int out_size) {
    const float* gene = (const float*)d_in[0];
    const float* mask = (const float*)d_in[1];
    const float* W1   = (const float*)d_in[2];
    const float* b1   = (const float*)d_in[3];
    const float* W2   = (const float*)d_in[4];
    const float* b2   = (const float*)d_in[5];
    const float* Wd   = (const float*)d_in[6];
    const float* bd   = (const float*)d_in[7];
    const void*  edges = d_in[8];
    const void*  perm  = d_in[9];

    float* out    = (float*)d_out;
    float* out_x1 = out;
    float* out_r1 = out + NN * H2D;
    float* out_rc = out + NN * H2D + NN * 2;

    const int SMEM_TC = NSTG * STAGEB;       // 92160 B dynamic
    cudaFuncSetAttribute(k_gemm1_tc,
                         cudaFuncAttributeMaxDynamicSharedMemorySize, SMEM_TC);

    k_init0det <<<EE / 256, 256>>>(edges);
    k_convA    <<<NN * (KPAD/8) / 256, 256>>>(gene);
    k_convB    <<<H1D * (KPAD/8) / 256, 256>>>(W1);

    dim3 gg1(H1D / 128, NN / 64);            // (2, 128) = 256 CTAs — launch #4
    k_gemm1_tc <<<gg1, 256, SMEM_TC>>>();

    k_perm_int <<<NN / 256, 256>>>(perm);
    k_deg_count<<<EE / 256, 256>>>(edges);
    k_dinv     <<<NN / 256, 256>>>();
    k_scan     <<<1, 256>>>();
    k_fill     <<<EE / 256, 256>>>(edges);

    k_gather1  <<<NN / 2, 128>>>(b1);
    k_gemm2    <<<128, 256>>>(W2);
    k_gather2  <<<NN / 16, 256>>>(b2, out_x1);

    k_readout  <<<NN, 256>>>(mask, out_x1);
    k_bilinear <<<NN, 64>>>(Wd, bd, out_x1, out_r1, out_rc);
}

// round 15
// speedup vs baseline: 1.6122x; 1.0448x over previous
#include <cuda_runtime.h>
#include <cuda_bf16.h>
#include <math.h>

#define NN   8192
#define EE   131072
#define IND  3000
#define H1D  256
#define H2D  64
#define KPAD 3008            // 94 * 32
#define CH   32              // K per smem stage
#define NST  (KPAD/CH)       // 94
#define SROW 40              // smem row stride in bf16 (80B: conflict-free ldmatrix)
#define OFF_AH 0
#define OFF_AL 5120          // 64*80
#define OFF_BH 10240
#define OFF_BL 20480
#define STAGEB 30720
#define NSTG 3
#define MCAP 64              // max nonzeros per mask row (mean ~17)

typedef unsigned long long u64;
typedef unsigned u32;

// ---------------- scratch ----------------
__device__ float g_XW   [NN*H1D];
__device__ float g_H1   [NN*H1D];
__device__ float g_H1c  [NN*H1D];
__device__ float g_XW2  [NN*H2D];
__device__ float g_XW2c [NN*H2D];
__device__ float g_X2c  [NN*H2D];
__device__ float g_dinv [NN];
__device__ int   g_deg  [NN];
__device__ int   g_off  [NN+1];
__device__ int   g_fill [NN];
__device__ int   g_permI[NN];
__device__ int   g_csr_src [EE];
__device__ int   g_csr_psrc[EE];
__device__ float g_csr_nm  [EE];
__device__ int   g_notI64;
__device__ __nv_bfloat16 g_Ah[(size_t)NN*KPAD];
__device__ __nv_bfloat16 g_Al[(size_t)NN*KPAD];
__device__ __nv_bfloat16 g_Bh[(size_t)H1D*KPAD];
__device__ __nv_bfloat16 g_Bl[(size_t)H1D*KPAD];
__device__ int   g_midx[NN*MCAP];
__device__ float g_mval[NN*MCAP];
__device__ int   g_mcnt[NN];
__device__ float g_mrs [NN];

// ---------------- helpers ----------------
__device__ __forceinline__ u64 pack2(float x) {
    u64 r; asm("mov.b64 %0, {%1, %1};" : "=l"(r) : "f"(x)); return r;
}
__device__ __forceinline__ void fma2(u64& d, u64 a, u64 b) {
    asm("fma.rn.f32x2 %0, %1, %2, %0;" : "+l"(d) : "l"(a), "l"(b));
}
__device__ __forceinline__ u32 smem_u32(const void* p) {
    u32 a;
    asm("{ .reg .u64 t; cvta.to.shared.u64 t, %1; cvt.u32.u64 %0, t; }"
        : "=r"(a) : "l"(p));
    return a;
}
__device__ __forceinline__ void ldm_x4(u32* r, u32 addr) {
    asm volatile("ldmatrix.sync.aligned.m8n8.x4.shared.b16 {%0,%1,%2,%3}, [%4];"
                 : "=r"(r[0]), "=r"(r[1]), "=r"(r[2]), "=r"(r[3]) : "r"(addr));
}
__device__ __forceinline__ void mma_bf16(float* d, const u32* a, u32 b0, u32 b1) {
    asm volatile(
        "mma.sync.aligned.m16n8k16.row.col.f32.bf16.bf16.f32 "
        "{%0,%1,%2,%3}, {%4,%5,%6,%7}, {%8,%9}, {%0,%1,%2,%3};"
        : "+f"(d[0]), "+f"(d[1]), "+f"(d[2]), "+f"(d[3])
        : "r"(a[0]), "r"(a[1]), "r"(a[2]), "r"(a[3]), "r"(b0), "r"(b1));
}
__device__ __forceinline__ void cp16(u32 dst, const void* src) {
    asm volatile("cp.async.cg.shared.global [%0], [%1], 16;"
                 :: "r"(dst), "l"(src) : "memory");
}
#define CP_COMMIT() asm volatile("cp.async.commit_group;" ::: "memory")
#define CP_WAIT1()  asm volatile("cp.async.wait_group 1;" ::: "memory")
__device__ __forceinline__ int idx_at(const void* p, int i, int is64) {
    return is64 ? (int)((const long long*)p)[i] : ((const int*)p)[i];
}

// ---------------- mask scan: compact nnz + row sums (fork stream 1) --
__global__ void k_maskscan(const float* __restrict__ mask) {
    __shared__ int   s_cnt;
    __shared__ float s_rs;
    int i = blockIdx.x;
    int tid = threadIdx.x;  // 256
    if (tid == 0) { s_cnt = 0; s_rs = 0.f; }
    __syncthreads();
    float rs = 0.f;
    const float4* m4 = (const float4*)&mask[(size_t)i * NN];
    for (int j4 = tid; j4 < NN / 4; j4 += 256) {
        float4 m = m4[j4];
        rs += m.x + m.y + m.z + m.w;
        float mv[4] = {m.x, m.y, m.z, m.w};
#pragma unroll
        for (int q = 0; q < 4; q++)
            if (mv[q] != 0.f) {
                int p = atomicAdd(&s_cnt, 1);
                if (p < MCAP) { g_midx[i*MCAP + p] = j4*4 + q; g_mval[i*MCAP + p] = mv[q]; }
            }
    }
#pragma unroll
    for (int o = 16; o; o >>= 1) rs += __shfl_down_sync(0xFFFFFFFFu, rs, o);
    if ((tid & 31) == 0) atomicAdd(&s_rs, rs);
    __syncthreads();
    if (tid == 0) {
        g_mcnt[i] = s_cnt < MCAP ? s_cnt : MCAP;
        g_mrs[i]  = s_rs;
    }
}

// ---------------- setup: deg init + dtype detect (fork stream 2) ----
__global__ void k_init0det(const void* edges) {
    int i = blockIdx.x * blockDim.x + threadIdx.x;   // grid covers EE
    if (i < NN) g_deg[i] = 1;
    const long long* p = (const long long*)edges;
    long long v = p[i];
    if (v < 0 || v >= NN) g_notI64 = 1;
}
__global__ void k_perm_int(const void* permp) {
    int i = blockIdx.x * blockDim.x + threadIdx.x;
    if (i < NN) g_permI[i] = idx_at(permp, i, !g_notI64);
}
__global__ void k_deg_count(const void* edges) {
    int e = blockIdx.x * blockDim.x + threadIdx.x;
    if (e >= EE) return;
    atomicAdd(&g_deg[idx_at(edges, EE + e, !g_notI64)], 1);
}
__global__ void k_dinv() {
    int i = blockIdx.x * blockDim.x + threadIdx.x;
    if (i < NN) g_dinv[i] = rsqrtf((float)g_deg[i]);
}
__global__ void k_scan() {
    __shared__ int partial[256];
    int t = threadIdx.x;
    int base = t * 32;
    int local[32];
    int sum = 0;
#pragma unroll
    for (int j = 0; j < 32; j++) {
        int c = g_deg[base + j] - 1;
        local[j] = sum;
        sum += c;
    }
    partial[t] = sum;
    __syncthreads();
    for (int o = 1; o < 256; o <<= 1) {
        int u = (t >= o) ? partial[t - o] : 0;
        __syncthreads();
        partial[t] += u;
        __syncthreads();
    }
    int off0 = partial[t] - sum;
#pragma unroll
    for (int j = 0; j < 32; j++) {
        int o = off0 + local[j];
        g_off[base + j]  = o;
        g_fill[base + j] = o;
    }
    if (t == 255) g_off[NN] = partial[255];
}
__global__ void k_fill(const void* edges) {
    int e = blockIdx.x * blockDim.x + threadIdx.x;
    if (e >= EE) return;
    int is64 = !g_notI64;
    int s = idx_at(edges, e, is64);
    int d = idx_at(edges, EE + e, is64);
    int pos = atomicAdd(&g_fill[d], 1);
    g_csr_src [pos] = s;
    g_csr_psrc[pos] = g_permI[s];
    g_csr_nm  [pos] = g_dinv[s] * g_dinv[d];
}

// ---------------- bf16 hi/lo split conversions ----------------------
__global__ void k_convA(const float* __restrict__ A) {
    int idx = blockIdx.x * 256 + threadIdx.x;
    int m = idx / (KPAD/8), g = idx % (KPAD/8);
    int k = g * 8;
    __align__(16) __nv_bfloat16 h[8], l[8];
    if (k < IND) {
        const float* p = A + (size_t)m * IND + k;
#pragma unroll
        for (int j = 0; j < 8; j++) {
            float v = p[j];
            __nv_bfloat16 hh = __float2bfloat16(v);
            h[j] = hh;
            l[j] = __float2bfloat16(v - __bfloat162float(hh));
        }
    } else {
#pragma unroll
        for (int j = 0; j < 8; j++) { h[j] = __float2bfloat16(0.f); l[j] = h[j]; }
    }
    *(uint4*)&g_Ah[(size_t)m * KPAD + k] = *(uint4*)h;
    *(uint4*)&g_Al[(size_t)m * KPAD + k] = *(uint4*)l;
}
__global__ void k_convB(const float* __restrict__ W1) {
    int idx = blockIdx.x * 256 + threadIdx.x;
    int n = idx / (KPAD/8), g = idx % (KPAD/8);
    int k = g * 8;
    __align__(16) __nv_bfloat16 h[8], l[8];
#pragma unroll
    for (int j = 0; j < 8; j++) {
        int kk = k + j;
        float v = (kk < IND) ? W1[(size_t)kk * H1D + n] : 0.f;
        __nv_bfloat16 hh = __float2bfloat16(v);
        h[j] = hh;
        l[j] = __float2bfloat16(v - __bfloat162float(hh));
    }
    *(uint4*)&g_Bh[(size_t)n * KPAD + k] = *(uint4*)h;
    *(uint4*)&g_Bl[(size_t)n * KPAD + k] = *(uint4*)l;
}

// ---------------- GEMM1 via mma.sync bf16 (3-term split) -----------
__global__ void __launch_bounds__(256, 2)
k_gemm1_tc() {
    extern __shared__ char smem[];
    u32 sb = smem_u32(smem);
    int tid = threadIdx.x;
    int wid = tid >> 5, lane = tid & 31;
    int wm = wid & 1, wn = wid >> 1;
    int m0 = blockIdx.y * 64;
    int n0 = blockIdx.x * 128;

    u32 sdst[6];
    size_t goff[6];
    const __nv_bfloat16* gm[6];
#pragma unroll
    for (int q = 0; q < 6; q++) {
        int idx = q * 256 + tid;
        int matoff, chunk, grow;
        if (idx < 512) {
            matoff = (idx < 256) ? OFF_AH : OFF_AL;
            gm[q]  = (idx < 256) ? g_Ah : g_Al;
            chunk  = idx & 255;
            grow   = m0 + (chunk >> 2);
        } else {
            int r2 = idx - 512;
            matoff = (r2 < 512) ? OFF_BH : OFF_BL;
            gm[q]  = (r2 < 512) ? g_Bh : g_Bl;
            chunk  = r2 & 511;
            grow   = n0 + (chunk >> 2);
        }
        sdst[q] = (u32)(matoff + (chunk >> 2) * (SROW*2) + (chunk & 3) * 16);
        goff[q] = (size_t)grow * KPAD + (chunk & 3) * 8;
    }

    u32 aBase = (u32)((wm*32 + (lane & 15)) * (SROW*2) + (lane >> 4) * 16);
    u32 bBase = (u32)((wn*32 + ((lane >> 4) * 8) + (lane & 7)) * (SROW*2)
                      + ((lane >> 3) & 1) * 16);

    float acc[2][4][4];
#pragma unroll
    for (int i = 0; i < 2; i++)
#pragma unroll
        for (int j = 0; j < 4; j++)
#pragma unroll
            for (int q = 0; q < 4; q++) acc[i][j][q] = 0.f;

#pragma unroll
    for (int s = 0; s < 2; s++) {
        size_t ko = (size_t)s * CH;
#pragma unroll
        for (int q = 0; q < 6; q++)
            cp16(sb + s * STAGEB + sdst[q], &gm[q][goff[q] + ko]);
        CP_COMMIT();
    }

    for (int c = 0; c < NST; c++) {
        CP_WAIT1();
        __syncthreads();
        u32 bufb = sb + (c % NSTG) * STAGEB;
#pragma unroll
        for (int ks = 0; ks < 2; ks++) {
            u32 ko = ks * 32;
            u32 ah[2][4], al[2][4], bh[2][4], bl[2][4];
#pragma unroll
            for (int mt = 0; mt < 2; mt++) {
                u32 ao = bufb + aBase + mt * (16*SROW*2) + ko;
                ldm_x4(ah[mt], ao);
                ldm_x4(al[mt], ao + (OFF_AL - OFF_AH));
            }
#pragma unroll
            for (int t = 0; t < 2; t++) {
                u32 bo = bufb + OFF_BH + bBase + t * (16*SROW*2) + ko;
                ldm_x4(bh[t], bo);
                ldm_x4(bl[t], bo + (OFF_BL - OFF_BH));
            }
#pragma unroll
            for (int mt = 0; mt < 2; mt++)
#pragma unroll
                for (int nt = 0; nt < 4; nt++)
                    mma_bf16(acc[mt][nt], ah[mt], bh[nt>>1][(nt&1)*2], bh[nt>>1][(nt&1)*2+1]);
#pragma unroll
            for (int mt = 0; mt < 2; mt++)
#pragma unroll
                for (int nt = 0; nt < 4; nt++)
                    mma_bf16(acc[mt][nt], ah[mt], bl[nt>>1][(nt&1)*2], bl[nt>>1][(nt&1)*2+1]);
#pragma unroll
            for (int mt = 0; mt < 2; mt++)
#pragma unroll
                for (int nt = 0; nt < 4; nt++)
                    mma_bf16(acc[mt][nt], al[mt], bh[nt>>1][(nt&1)*2], bh[nt>>1][(nt&1)*2+1]);
        }
        if (c + 2 < NST) {
            size_t ko = (size_t)(c + 2) * CH;
            u32 nb = sb + ((c + 2) % NSTG) * STAGEB;
#pragma unroll
            for (int q = 0; q < 6; q++)
                cp16(nb + sdst[q], &gm[q][goff[q] + ko]);
        }
        CP_COMMIT();
        __syncthreads();
    }

    int er = lane >> 2, ec = (lane & 3) * 2;
#pragma unroll
    for (int mt = 0; mt < 2; mt++) {
#pragma unroll
        for (int nt = 0; nt < 4; nt++) {
            int row = m0 + wm*32 + mt*16 + er;
            int col = n0 + wn*32 + nt*8 + ec;
            *(float2*)&g_XW[(size_t)row * H1D + col] =
                make_float2(acc[mt][nt][0], acc[mt][nt][1]);
            *(float2*)&g_XW[(size_t)(row + 8) * H1D + col] =
                make_float2(acc[mt][nt][2], acc[mt][nt][3]);
        }
    }
}

// ---------------- conv1 gather ----------------
__global__ void k_gather1(const float* __restrict__ b1) {
    int tid = threadIdx.x;            // 128
    int i = blockIdx.x * 2 + (tid >> 6);
    int l = (tid & 63) * 4;
    float s2 = g_dinv[i] * g_dinv[i];
    int pi = g_permI[i];
    float4 x0 = *(const float4*)&g_XW[(size_t)i  * H1D + l];
    float4 xp = *(const float4*)&g_XW[(size_t)pi * H1D + l];
    float4 acc  = make_float4(s2*x0.x, s2*x0.y, s2*x0.z, s2*x0.w);
    float4 accc = make_float4(s2*xp.x, s2*xp.y, s2*xp.z, s2*xp.w);
    int e1 = g_off[i + 1];
    for (int e = g_off[i]; e < e1; e++) {
        int s  = g_csr_src[e];
        int ps = g_csr_psrc[e];
        float nm = g_csr_nm[e];
        float4 xs = *(const float4*)&g_XW[(size_t)s  * H1D + l];
        float4 xq = *(const float4*)&g_XW[(size_t)ps * H1D + l];
        acc.x  += nm*xs.x; acc.y  += nm*xs.y; acc.z  += nm*xs.z; acc.w  += nm*xs.w;
        accc.x += nm*xq.x; accc.y += nm*xq.y; accc.z += nm*xq.z; accc.w += nm*xq.w;
    }
    float4 bb = *(const float4*)&b1[l];
    float4 v;
    v.x = fmaxf(acc.x + bb.x, 0.f); v.y = fmaxf(acc.y + bb.y, 0.f);
    v.z = fmaxf(acc.z + bb.z, 0.f); v.w = fmaxf(acc.w + bb.w, 0.f);
    *(float4*)&g_H1[(size_t)i * H1D + l] = v;
    v.x = fmaxf(accc.x + bb.x, 0.f); v.y = fmaxf(accc.y + bb.y, 0.f);
    v.z = fmaxf(accc.z + bb.z, 0.f); v.w = fmaxf(accc.w + bb.w, 0.f);
    *(float4*)&g_H1c[(size_t)i * H1D + l] = v;
}

// ---------------- GEMM2: [2*8192,256]@[256,64] ----------------------
__global__ void __launch_bounds__(256, 1)
k_gemm2(const float* __restrict__ W2) {
    const float* Am = (blockIdx.x < 64) ? g_H1  : g_H1c;
    float*       Om = (blockIdx.x < 64) ? g_XW2 : g_XW2c;
    int m0 = (blockIdx.x & 63) * 128;

    __shared__ float As[2][8][128];
    __shared__ float Bs[2][8][64];
    int tid = threadIdx.x;
    int ty = tid >> 4, tx = tid & 15;
    int ar = tid >> 1, ak = (tid & 1) * 4;
    int br = tid >> 5, bc = (tid & 31) * 2;
    const float* Aptr = Am + (size_t)(m0 + ar) * H1D + ak;
    const float* Bptr = W2 + (size_t)br * H2D + bc;

    u64 acc[8][2];
#pragma unroll
    for (int i = 0; i < 8; i++) { acc[i][0] = 0ull; acc[i][1] = 0ull; }

    float4 a0 = *(const float4*)Aptr;
    float2 b0 = *(const float2*)Bptr;
    As[0][ak+0][ar] = a0.x; As[0][ak+1][ar] = a0.y;
    As[0][ak+2][ar] = a0.z; As[0][ak+3][ar] = a0.w;
    *(float2*)&Bs[0][br][bc] = b0;
    __syncthreads();

    int buf = 0;
    for (int k0 = 8; k0 < H1D; k0 += 8) {
        float4 an = *(const float4*)(Aptr + k0);
        float2 bn = *(const float2*)(Bptr + (size_t)k0 * H2D);
#pragma unroll
        for (int kk = 0; kk < 8; kk++) {
            float ra[8];
            *(float4*)&ra[0] = *(const float4*)&As[buf][kk][ty*8];
            *(float4*)&ra[4] = *(const float4*)&As[buf][kk][ty*8+4];
            ulonglong2 rb = *(const ulonglong2*)&Bs[buf][kk][tx*4];
#pragma unroll
            for (int i = 0; i < 8; i++) {
                u64 aa = pack2(ra[i]);
                fma2(acc[i][0], aa, rb.x);
                fma2(acc[i][1], aa, rb.y);
            }
        }
        buf ^= 1;
        As[buf][ak+0][ar] = an.x; As[buf][ak+1][ar] = an.y;
        As[buf][ak+2][ar] = an.z; As[buf][ak+3][ar] = an.w;
        *(float2*)&Bs[buf][br][bc] = bn;
        __syncthreads();
    }
#pragma unroll
    for (int kk = 0; kk < 8; kk++) {
        float ra[8];
        *(float4*)&ra[0] = *(const float4*)&As[buf][kk][ty*8];
        *(float4*)&ra[4] = *(const float4*)&As[buf][kk][ty*8+4];
        ulonglong2 rb = *(const ulonglong2*)&Bs[buf][kk][tx*4];
#pragma unroll
        for (int i = 0; i < 8; i++) {
            u64 aa = pack2(ra[i]);
            fma2(acc[i][0], aa, rb.x);
            fma2(acc[i][1], aa, rb.y);
        }
    }

#pragma unroll
    for (int i = 0; i < 8; i++) {
        ulonglong2 v; v.x = acc[i][0]; v.y = acc[i][1];
        *(ulonglong2*)&Om[(size_t)(m0 + ty*8 + i) * H2D + tx*4] = v;
    }
}

// ---------------- conv2 gather ----------------
__global__ void k_gather2(const float* __restrict__ b2, float* __restrict__ out_x1) {
    int t = threadIdx.x;            // 256
    int i = blockIdx.x * 16 + (t >> 4);
    int l = (t & 15) * 4;
    float s2 = g_dinv[i] * g_dinv[i];
    float4 x0 = *(const float4*)&g_XW2 [(size_t)i * H2D + l];
    float4 xc = *(const float4*)&g_XW2c[(size_t)i * H2D + l];
    float4 acc  = make_float4(s2*x0.x, s2*x0.y, s2*x0.z, s2*x0.w);
    float4 accc = make_float4(s2*xc.x, s2*xc.y, s2*xc.z, s2*xc.w);
    int e1 = g_off[i + 1];
    for (int e = g_off[i]; e < e1; e++) {
        int s = g_csr_src[e];
        float nm = g_csr_nm[e];
        float4 xs = *(const float4*)&g_XW2 [(size_t)s * H2D + l];
        float4 xq = *(const float4*)&g_XW2c[(size_t)s * H2D + l];
        acc.x  += nm*xs.x; acc.y  += nm*xs.y; acc.z  += nm*xs.z; acc.w  += nm*xs.w;
        accc.x += nm*xq.x; accc.y += nm*xq.y; accc.z += nm*xq.z; accc.w += nm*xq.w;
    }
    float4 bb = *(const float4*)&b2[l];
    float4 v;
    v.x = fmaxf(acc.x + bb.x, 0.f); v.y = fmaxf(acc.y + bb.y, 0.f);
    v.z = fmaxf(acc.z + bb.z, 0.f); v.w = fmaxf(acc.w + bb.w, 0.f);
    *(float4*)&out_x1[(size_t)i * H2D + l] = v;
    v.x = fmaxf(accc.x + bb.x, 0.f); v.y = fmaxf(accc.y + bb.y, 0.f);
    v.z = fmaxf(accc.z + bb.z, 0.f); v.w = fmaxf(accc.w + bb.w, 0.f);
    *(float4*)&g_X2c[(size_t)i * H2D + l] = v;
}

// ---------------- readout2: gather + normalize + sigmoid + bilinear -
__global__ void k_readout2(const float* __restrict__ Wd, const float* __restrict__ bd,
                           const float* __restrict__ x1,
                           float* __restrict__ ret1, float* __restrict__ ret1c) {
    __shared__ float part1[4][H2D], part2[4][H2D];
    __shared__ float c1[H2D], c2[H2D], h[H2D], hc[H2D];
    __shared__ float red[4][H2D];
    __shared__ float nrm1, nrm2;
    int i = blockIdx.x;
    int tid = threadIdx.x;  // 256
    int cnt = g_mcnt[i];
    float inv = 1.0f / g_mrs[i];

    int g = tid >> 6, f = tid & 63;
    float a1 = 0.f, a2 = 0.f;
    for (int e = g; e < cnt; e += 4) {
        int j = g_midx[i*MCAP + e];
        float mv = g_mval[i*MCAP + e];
        a1 += mv * x1   [(size_t)j * H2D + f];
        a2 += mv * g_X2c[(size_t)j * H2D + f];
    }
    part1[g][f] = a1;
    part2[g][f] = a2;
    __syncthreads();

    if (tid < H2D) {
        c1[tid] = (part1[0][tid] + part1[1][tid] + part1[2][tid] + part1[3][tid]) * inv;
        c2[tid] = (part2[0][tid] + part2[1][tid] + part2[2][tid] + part2[3][tid]) * inv;
        h [tid] = x1   [(size_t)i*H2D + tid];
        hc[tid] = g_X2c[(size_t)i*H2D + tid];
    }
    __syncthreads();
    if (tid == 0) {
        float s1 = 0.f, s2 = 0.f;
        for (int q = 0; q < H2D; q++) { s1 += c1[q]*c1[q]; s2 += c2[q]*c2[q]; }
        nrm1 = fmaxf(sqrtf(s1), 1e-12f);
        nrm2 = fmaxf(sqrtf(s2), 1e-12f);
    }
    __syncthreads();
    if (tid < H2D) {
        c1[tid] = 1.0f / (1.0f + expf(-c1[tid] / nrm1));
        c2[tid] = 1.0f / (1.0f + expf(-c2[tid] / nrm2));
    }
    __syncthreads();
    if (tid < H2D) {
        int k = tid;
        float t1 = 0.f, t2 = 0.f;
        const float4* wr = (const float4*)&Wd[k * H2D];
#pragma unroll
        for (int j4 = 0; j4 < H2D / 4; j4++) {
            float4 w = wr[j4];
            t1 += w.x*c1[j4*4] + w.y*c1[j4*4+1] + w.z*c1[j4*4+2] + w.w*c1[j4*4+3];
            t2 += w.x*c2[j4*4] + w.y*c2[j4*4+1] + w.z*c2[j4*4+2] + w.w*c2[j4*4+3];
        }
        red[0][k] = h [k] * t1;
        red[1][k] = hc[k] * t1;
        red[2][k] = hc[k] * t2;
        red[3][k] = h [k] * t2;
    }
    __syncthreads();
    if (tid < 4) {
        float s = 0.f;
        for (int j = 0; j < H2D; j++) s += red[tid][j];
        s += bd[0];
        if (tid == 0) ret1 [i*2 + 0] = s;
        if (tid == 1) ret1 [i*2 + 1] = s;
        if (tid == 2) ret1c[i*2 + 0] = s;
        if (tid == 3) ret1c[i*2 + 1] = s;
    }
}

// ---------------- launch ----------------
extern "C" void kernel_launch(void* const* d_in, const int* in_sizes, int n_in,
                              void* d_out, int out_size) {
    const float* gene = (const float*)d_in[0];
    const float* mask = (const float*)d_in[1];
    const float* W1   = (const float*)d_in[2];
    const float* b1   = (const float*)d_in[3];
    const float* W2   = (const float*)d_in[4];
    const float* b2   = (const float*)d_in[5];
    const float* Wd   = (const float*)d_in[6];
    const float* bd   = (const float*)d_in[7];
    const void*  edges = d_in[8];
    const void*  perm  = d_in[9];

    float* out    = (float*)d_out;
    float* out_x1 = out;
    float* out_r1 = out + NN * H2D;
    float* out_rc = out + NN * H2D + NN * 2;

    static cudaStream_t s1 = 0, s2 = 0;
    static cudaEvent_t evRoot = 0, evS1 = 0, evS2 = 0;
    static int inited = 0;
    if (!inited) {
        cudaStreamCreateWithFlags(&s1, cudaStreamNonBlocking);
        cudaStreamCreateWithFlags(&s2, cudaStreamNonBlocking);
        cudaEventCreateWithFlags(&evRoot, cudaEventDisableTiming);
        cudaEventCreateWithFlags(&evS1,   cudaEventDisableTiming);
        cudaEventCreateWithFlags(&evS2,   cudaEventDisableTiming);
        cudaFuncSetAttribute(k_gemm1_tc,
                             cudaFuncAttributeMaxDynamicSharedMemorySize, NSTG * STAGEB);
        inited = 1;
    }

    // fork: s1 = mask scan, s2 = edge/CSR setup; main = conv + gemm1
    cudaEventRecord(evRoot, 0);
    cudaStreamWaitEvent(s1, evRoot, 0);
    cudaStreamWaitEvent(s2, evRoot, 0);

    k_maskscan <<<NN, 256, 0, s1>>>(mask);                 // #1

    k_convA    <<<NN * (KPAD/8) / 256, 256>>>(gene);       // #2
    k_convB    <<<H1D * (KPAD/8) / 256, 256>>>(W1);        // #3
    dim3 gg1(H1D / 128, NN / 64);                          // 256 CTAs
    k_gemm1_tc <<<gg1, 256, NSTG * STAGEB>>>();            // #4 (profiled)

    k_init0det <<<EE / 256, 256, 0, s2>>>(edges);
    k_perm_int <<<NN / 256, 256, 0, s2>>>(perm);
    k_deg_count<<<EE / 256, 256, 0, s2>>>(edges);
    k_dinv     <<<NN / 256, 256, 0, s2>>>();
    k_scan     <<<1, 256, 0, s2>>>();
    k_fill     <<<EE / 256, 256, 0, s2>>>(edges);

    // join
    cudaEventRecord(evS1, s1);
    cudaEventRecord(evS2, s2);
    cudaStreamWaitEvent(0, evS1, 0);
    cudaStreamWaitEvent(0, evS2, 0);

    k_gather1  <<<NN / 2, 128>>>(b1);
    k_gemm2    <<<128, 256>>>(W2);
    k_gather2  <<<NN / 16, 256>>>(b2, out_x1);
    k_readout2 <<<NN, 256>>>(Wd, bd, out_x1, out_r1, out_rc);
}

// round 17
// speedup vs baseline: 1.6638x; 1.0320x over previous
#include <cuda_runtime.h>
#include <cuda_bf16.h>
#include <math.h>

#define NN   8192
#define EE   131072
#define IND  3000
#define H1D  256
#define H2D  64
#define KPAD 3008            // 94 * 32
#define CH   32              // K per smem stage
#define NST  (KPAD/CH)       // 94
#define SROW 40              // smem row stride in bf16 (80B)
#define RAWROW 144           // raw fp32 A row stride (36 floats, 16B-aligned)
// stage layout: raw fp32 A (128 rows x 144B), then Ah,Al,Bh,Bl (80B rows)
#define OFF_AH 18432
#define OFF_AL 28672
#define OFF_BH 38912
#define OFF_BL 49152
#define STAGEB 59392
#define NSTG 3               // 178176 B dynamic smem, 1 CTA/SM
#define MCAP 64

typedef unsigned long long u64;
typedef unsigned u32;

// ---------------- scratch ----------------
__device__ float g_XW   [NN*H1D];
__device__ float g_H1   [NN*H1D];
__device__ float g_H1c  [NN*H1D];
__device__ float g_XW2  [NN*H2D];
__device__ float g_XW2c [NN*H2D];
__device__ float g_X2c  [NN*H2D];
__device__ float g_dinv [NN];
__device__ int   g_deg  [NN];
__device__ int   g_off  [NN+1];
__device__ int   g_fill [NN];
__device__ int   g_permI[NN];
__device__ int   g_csr_src [EE];
__device__ int   g_csr_psrc[EE];
__device__ float g_csr_nm  [EE];
__device__ int   g_notI64;
__device__ __nv_bfloat16 g_Bh[(size_t)H1D*KPAD];
__device__ __nv_bfloat16 g_Bl[(size_t)H1D*KPAD];
__device__ int   g_midx[NN*MCAP];
__device__ float g_mval[NN*MCAP];
__device__ int   g_mcnt[NN];
__device__ float g_mrs [NN];

// ---------------- helpers ----------------
__device__ __forceinline__ u64 pack2(float x) {
    u64 r; asm("mov.b64 %0, {%1, %1};" : "=l"(r) : "f"(x)); return r;
}
__device__ __forceinline__ void fma2(u64& d, u64 a, u64 b) {
    asm("fma.rn.f32x2 %0, %1, %2, %0;" : "+l"(d) : "l"(a), "l"(b));
}
__device__ __forceinline__ u32 smem_u32(const void* p) {
    u32 a;
    asm("{ .reg .u64 t; cvta.to.shared.u64 t, %1; cvt.u32.u64 %0, t; }"
        : "=r"(a) : "l"(p));
    return a;
}
__device__ __forceinline__ void ldm_x4(u32* r, u32 addr) {
    asm volatile("ldmatrix.sync.aligned.m8n8.x4.shared.b16 {%0,%1,%2,%3}, [%4];"
                 : "=r"(r[0]), "=r"(r[1]), "=r"(r[2]), "=r"(r[3]) : "r"(addr));
}
__device__ __forceinline__ void mma_bf16(float* d, const u32* a, u32 b0, u32 b1) {
    asm volatile(
        "mma.sync.aligned.m16n8k16.row.col.f32.bf16.bf16.f32 "
        "{%0,%1,%2,%3}, {%4,%5,%6,%7}, {%8,%9}, {%0,%1,%2,%3};"
        : "+f"(d[0]), "+f"(d[1]), "+f"(d[2]), "+f"(d[3])
        : "r"(a[0]), "r"(a[1]), "r"(a[2]), "r"(a[3]), "r"(b0), "r"(b1));
}
__device__ __forceinline__ void cp16(u32 dst, const void* src) {
    asm volatile("cp.async.cg.shared.global [%0], [%1], 16;"
                 :: "r"(dst), "l"(src) : "memory");
}
#define CP_COMMIT() asm volatile("cp.async.commit_group;" ::: "memory")
#define CP_WAIT1()  asm volatile("cp.async.wait_group 1;" ::: "memory")
__device__ __forceinline__ int idx_at(const void* p, int i, int is64) {
    return is64 ? (int)((const long long*)p)[i] : ((const int*)p)[i];
}

// ---------------- mask scan (fork stream 1) ----------------
__global__ void k_maskscan(const float* __restrict__ mask) {
    __shared__ int   s_cnt;
    __shared__ float s_rs;
    int i = blockIdx.x;
    int tid = threadIdx.x;  // 256
    if (tid == 0) { s_cnt = 0; s_rs = 0.f; }
    __syncthreads();
    float rs = 0.f;
    const float4* m4 = (const float4*)&mask[(size_t)i * NN];
    for (int j4 = tid; j4 < NN / 4; j4 += 256) {
        float4 m = m4[j4];
        rs += m.x + m.y + m.z + m.w;
        float mv[4] = {m.x, m.y, m.z, m.w};
#pragma unroll
        for (int q = 0; q < 4; q++)
            if (mv[q] != 0.f) {
                int p = atomicAdd(&s_cnt, 1);
                if (p < MCAP) { g_midx[i*MCAP + p] = j4*4 + q; g_mval[i*MCAP + p] = mv[q]; }
            }
    }
#pragma unroll
    for (int o = 16; o; o >>= 1) rs += __shfl_down_sync(0xFFFFFFFFu, rs, o);
    if ((tid & 31) == 0) atomicAdd(&s_rs, rs);
    __syncthreads();
    if (tid == 0) {
        g_mcnt[i] = s_cnt < MCAP ? s_cnt : MCAP;
        g_mrs[i]  = s_rs;
    }
}

// ---------------- setup (fork stream 2) ----------------
__global__ void k_init0det(const void* edges) {
    int i = blockIdx.x * blockDim.x + threadIdx.x;
    if (i < NN) g_deg[i] = 1;
    const long long* p = (const long long*)edges;
    long long v = p[i];
    if (v < 0 || v >= NN) g_notI64 = 1;
}
__global__ void k_perm_int(const void* permp) {
    int i = blockIdx.x * blockDim.x + threadIdx.x;
    if (i < NN) g_permI[i] = idx_at(permp, i, !g_notI64);
}
__global__ void k_deg_count(const void* edges) {
    int e = blockIdx.x * blockDim.x + threadIdx.x;
    if (e >= EE) return;
    atomicAdd(&g_deg[idx_at(edges, EE + e, !g_notI64)], 1);
}
__global__ void k_dinv() {
    int i = blockIdx.x * blockDim.x + threadIdx.x;
    if (i < NN) g_dinv[i] = rsqrtf((float)g_deg[i]);
}
__global__ void k_scan() {
    __shared__ int partial[256];
    int t = threadIdx.x;
    int base = t * 32;
    int local[32];
    int sum = 0;
#pragma unroll
    for (int j = 0; j < 32; j++) {
        int c = g_deg[base + j] - 1;
        local[j] = sum;
        sum += c;
    }
    partial[t] = sum;
    __syncthreads();
    for (int o = 1; o < 256; o <<= 1) {
        int u = (t >= o) ? partial[t - o] : 0;
        __syncthreads();
        partial[t] += u;
        __syncthreads();
    }
    int off0 = partial[t] - sum;
#pragma unroll
    for (int j = 0; j < 32; j++) {
        int o = off0 + local[j];
        g_off[base + j]  = o;
        g_fill[base + j] = o;
    }
    if (t == 255) g_off[NN] = partial[255];
}
__global__ void k_fill(const void* edges) {
    int e = blockIdx.x * blockDim.x + threadIdx.x;
    if (e >= EE) return;
    int is64 = !g_notI64;
    int s = idx_at(edges, e, is64);
    int d = idx_at(edges, EE + e, is64);
    int pos = atomicAdd(&g_fill[d], 1);
    g_csr_src [pos] = s;
    g_csr_psrc[pos] = g_permI[s];
    g_csr_nm  [pos] = g_dinv[s] * g_dinv[d];
}

// ---------------- bf16 hi/lo split for B only ------------------------
__global__ void k_convB(const float* __restrict__ W1) {
    int idx = blockIdx.x * 256 + threadIdx.x;        // H1D * (KPAD/8)
    int n = idx / (KPAD/8), g = idx % (KPAD/8);
    int k = g * 8;
    __align__(16) __nv_bfloat16 h[8], l[8];
#pragma unroll
    for (int j = 0; j < 8; j++) {
        int kk = k + j;
        float v = (kk < IND) ? W1[(size_t)kk * H1D + n] : 0.f;
        __nv_bfloat16 hh = __float2bfloat16(v);
        h[j] = hh;
        l[j] = __float2bfloat16(v - __bfloat162float(hh));
    }
    *(uint4*)&g_Bh[(size_t)n * KPAD + k] = *(uint4*)h;
    *(uint4*)&g_Bl[(size_t)n * KPAD + k] = *(uint4*)l;
}

// ---------------- GEMM1: fused fp32->bf16 split + mma.sync ----------
// CTA 128x128, 8 warps (warp tile 64x32), 3-stage ring. A loaded raw
// fp32 via cp.async (row stride 144B, 16B-aligned), converted to Ah/Al
// in-kernel. A cols 3000..3007 multiply zero-padded B rows -> exact.
__global__ void __launch_bounds__(256, 1)
k_gemm1_tc(const float* __restrict__ A) {
    extern __shared__ char smem[];
    u32 sb = smem_u32(smem);
    int tid = threadIdx.x;
    int wid = tid >> 5, lane = tid & 31;
    int wm = wid & 1, wn = wid >> 1;        // 2(M) x 4(N) warps
    int m0 = blockIdx.y * 128;
    int n0 = blockIdx.x * 128;

    // cp.async descriptors: 8 x 16B per thread per stage (2048 chunks)
    //  q 0..3: raw fp32 A (128 rows x 8 chunks), q 4..7: Bh/Bl (128 rows x 4 x 2)
    const char* gbase[8];
    u32 sdst[8], gstep[8];
    size_t goff[8];
    const size_t LIMB = ((size_t)NN * IND - 4) * 4;  // last safe 16B fp32 read
#pragma unroll
    for (int q = 0; q < 8; q++) {
        int idx = q * 256 + tid;
        if (idx < 1024) {                     // raw A
            int row = idx >> 3, ch = idx & 7;
            sdst[q]  = (u32)(row * RAWROW + ch * 16);
            gbase[q] = (const char*)A;
            goff[q]  = ((size_t)(m0 + row) * IND + ch * 4) * 4;
            gstep[q] = CH * 4;                // 128 B per stage
        } else {
            int j = idx - 1024;
            int mat = j >> 9;                 // 0: Bh, 1: Bl
            int r2 = j & 511;
            int row = r2 >> 2, ch = r2 & 3;
            sdst[q]  = (u32)((mat ? OFF_BL : OFF_BH) + row * (SROW*2) + ch * 16);
            gbase[q] = (const char*)(mat ? g_Bl : g_Bh);
            goff[q]  = ((size_t)(n0 + row) * KPAD + ch * 8) * 2;
            gstep[q] = CH * 2;                // 64 B per stage
        }
    }

    // converter mapping: 16 floats per thread
    int cr = tid >> 1;                        // row 0..127
    int ck = (tid & 1) * 16;                  // k 0 or 16

    // ldmatrix lane bases
    u32 aBase = (u32)(OFF_AH + (wm*64 + (lane & 15)) * (SROW*2) + (lane >> 4) * 16);
    u32 bBase = (u32)(OFF_BH + (wn*32 + ((lane >> 4) * 8) + (lane & 7)) * (SROW*2)
                      + ((lane >> 3) & 1) * 16);

    float acc[4][4][4];
#pragma unroll
    for (int i = 0; i < 4; i++)
#pragma unroll
        for (int j = 0; j < 4; j++)
#pragma unroll
            for (int q = 0; q < 4; q++) acc[i][j][q] = 0.f;

    // preload stages 0,1
#pragma unroll
    for (int s = 0; s < 2; s++) {
#pragma unroll
        for (int q = 0; q < 8; q++) {
            size_t off = goff[q] + (size_t)s * gstep[q];
            if (q < 4 && off > LIMB) off = LIMB;
            cp16(sb + s * STAGEB + sdst[q], gbase[q] + off);
        }
        CP_COMMIT();
    }

    for (int c = 0; c < NST; c++) {
        CP_WAIT1();
        __syncthreads();
        u32 bufb = sb + (c % NSTG) * STAGEB;
        char* bufp = smem + (c % NSTG) * STAGEB;

        // convert raw fp32 -> Ah/Al (this thread's 16 floats)
        {
            const float* rp = (const float*)(bufp + cr * RAWROW + ck * 4);
            __align__(16) __nv_bfloat16 hh[16], ll[16];
#pragma unroll
            for (int j = 0; j < 16; j++) {
                float v = rp[j];
                __nv_bfloat16 hb = __float2bfloat16(v);
                hh[j] = hb;
                ll[j] = __float2bfloat16(v - __bfloat162float(hb));
            }
            uint4* oh = (uint4*)(bufp + OFF_AH + cr * (SROW*2) + ck * 2);
            uint4* ol = (uint4*)(bufp + OFF_AL + cr * (SROW*2) + ck * 2);
            oh[0] = ((uint4*)hh)[0]; oh[1] = ((uint4*)hh)[1];
            ol[0] = ((uint4*)ll)[0]; ol[1] = ((uint4*)ll)[1];
        }
        __syncthreads();

#pragma unroll
        for (int ks = 0; ks < 2; ks++) {
            u32 ko = ks * 32;
            u32 ah[4][4], al[4][4], bh[2][4], bl[2][4];
#pragma unroll
            for (int mt = 0; mt < 4; mt++) {
                u32 ao = bufb + aBase + mt * (16*SROW*2) + ko;
                ldm_x4(ah[mt], ao);
                ldm_x4(al[mt], ao + (OFF_AL - OFF_AH));
            }
#pragma unroll
            for (int t = 0; t < 2; t++) {
                u32 bo = bufb + bBase + t * (16*SROW*2) + ko;
                ldm_x4(bh[t], bo);
                ldm_x4(bl[t], bo + (OFF_BL - OFF_BH));
            }
            // term-major to break accumulator RAW chains
#pragma unroll
            for (int mt = 0; mt < 4; mt++)
#pragma unroll
                for (int nt = 0; nt < 4; nt++)
                    mma_bf16(acc[mt][nt], ah[mt], bh[nt>>1][(nt&1)*2], bh[nt>>1][(nt&1)*2+1]);
#pragma unroll
            for (int mt = 0; mt < 4; mt++)
#pragma unroll
                for (int nt = 0; nt < 4; nt++)
                    mma_bf16(acc[mt][nt], ah[mt], bl[nt>>1][(nt&1)*2], bl[nt>>1][(nt&1)*2+1]);
#pragma unroll
            for (int mt = 0; mt < 4; mt++)
#pragma unroll
                for (int nt = 0; nt < 4; nt++)
                    mma_bf16(acc[mt][nt], al[mt], bh[nt>>1][(nt&1)*2], bh[nt>>1][(nt&1)*2+1]);
        }
        if (c + 2 < NST) {
            u32 nb = sb + ((c + 2) % NSTG) * STAGEB;
#pragma unroll
            for (int q = 0; q < 8; q++) {
                size_t off = goff[q] + (size_t)(c + 2) * gstep[q];
                if (q < 4 && off > LIMB) off = LIMB;
                cp16(nb + sdst[q], gbase[q] + off);
            }
        }
        CP_COMMIT();
    }

    int er = lane >> 2, ec = (lane & 3) * 2;
#pragma unroll
    for (int mt = 0; mt < 4; mt++) {
#pragma unroll
        for (int nt = 0; nt < 4; nt++) {
            int row = m0 + wm*64 + mt*16 + er;
            int col = n0 + wn*32 + nt*8 + ec;
            *(float2*)&g_XW[(size_t)row * H1D + col] =
                make_float2(acc[mt][nt][0], acc[mt][nt][1]);
            *(float2*)&g_XW[(size_t)(row + 8) * H1D + col] =
                make_float2(acc[mt][nt][2], acc[mt][nt][3]);
        }
    }
}

// ---------------- conv1 gather ----------------
__global__ void k_gather1(const float* __restrict__ b1) {
    int tid = threadIdx.x;            // 128
    int i = blockIdx.x * 2 + (tid >> 6);
    int l = (tid & 63) * 4;
    float s2 = g_dinv[i] * g_dinv[i];
    int pi = g_permI[i];
    float4 x0 = *(const float4*)&g_XW[(size_t)i  * H1D + l];
    float4 xp = *(const float4*)&g_XW[(size_t)pi * H1D + l];
    float4 acc  = make_float4(s2*x0.x, s2*x0.y, s2*x0.z, s2*x0.w);
    float4 accc = make_float4(s2*xp.x, s2*xp.y, s2*xp.z, s2*xp.w);
    int e1 = g_off[i + 1];
    for (int e = g_off[i]; e < e1; e++) {
        int s  = g_csr_src[e];
        int ps = g_csr_psrc[e];
        float nm = g_csr_nm[e];
        float4 xs = *(const float4*)&g_XW[(size_t)s  * H1D + l];
        float4 xq = *(const float4*)&g_XW[(size_t)ps * H1D + l];
        acc.x  += nm*xs.x; acc.y  += nm*xs.y; acc.z  += nm*xs.z; acc.w  += nm*xs.w;
        accc.x += nm*xq.x; accc.y += nm*xq.y; accc.z += nm*xq.z; accc.w += nm*xq.w;
    }
    float4 bb = *(const float4*)&b1[l];
    float4 v;
    v.x = fmaxf(acc.x + bb.x, 0.f); v.y = fmaxf(acc.y + bb.y, 0.f);
    v.z = fmaxf(acc.z + bb.z, 0.f); v.w = fmaxf(acc.w + bb.w, 0.f);
    *(float4*)&g_H1[(size_t)i * H1D + l] = v;
    v.x = fmaxf(accc.x + bb.x, 0.f); v.y = fmaxf(accc.y + bb.y, 0.f);
    v.z = fmaxf(accc.z + bb.z, 0.f); v.w = fmaxf(accc.w + bb.w, 0.f);
    *(float4*)&g_H1c[(size_t)i * H1D + l] = v;
}

// ---------------- GEMM2 ----------------
__global__ void __launch_bounds__(256, 1)
k_gemm2(const float* __restrict__ W2) {
    const float* Am = (blockIdx.x < 64) ? g_H1  : g_H1c;
    float*       Om = (blockIdx.x < 64) ? g_XW2 : g_XW2c;
    int m0 = (blockIdx.x & 63) * 128;

    __shared__ float As[2][8][128];
    __shared__ float Bs[2][8][64];
    int tid = threadIdx.x;
    int ty = tid >> 4, tx = tid & 15;
    int ar = tid >> 1, ak = (tid & 1) * 4;
    int br = tid >> 5, bc = (tid & 31) * 2;
    const float* Aptr = Am + (size_t)(m0 + ar) * H1D + ak;
    const float* Bptr = W2 + (size_t)br * H2D + bc;

    u64 acc[8][2];
#pragma unroll
    for (int i = 0; i < 8; i++) { acc[i][0] = 0ull; acc[i][1] = 0ull; }

    float4 a0 = *(const float4*)Aptr;
    float2 b0 = *(const float2*)Bptr;
    As[0][ak+0][ar] = a0.x; As[0][ak+1][ar] = a0.y;
    As[0][ak+2][ar] = a0.z; As[0][ak+3][ar] = a0.w;
    *(float2*)&Bs[0][br][bc] = b0;
    __syncthreads();

    int buf = 0;
    for (int k0 = 8; k0 < H1D; k0 += 8) {
        float4 an = *(const float4*)(Aptr + k0);
        float2 bn = *(const float2*)(Bptr + (size_t)k0 * H2D);
#pragma unroll
        for (int kk = 0; kk < 8; kk++) {
            float ra[8];
            *(float4*)&ra[0] = *(const float4*)&As[buf][kk][ty*8];
            *(float4*)&ra[4] = *(const float4*)&As[buf][kk][ty*8+4];
            ulonglong2 rb = *(const ulonglong2*)&Bs[buf][kk][tx*4];
#pragma unroll
            for (int i = 0; i < 8; i++) {
                u64 aa = pack2(ra[i]);
                fma2(acc[i][0], aa, rb.x);
                fma2(acc[i][1], aa, rb.y);
            }
        }
        buf ^= 1;
        As[buf][ak+0][ar] = an.x; As[buf][ak+1][ar] = an.y;
        As[buf][ak+2][ar] = an.z; As[buf][ak+3][ar] = an.w;
        *(float2*)&Bs[buf][br][bc] = bn;
        __syncthreads();
    }
#pragma unroll
    for (int kk = 0; kk < 8; kk++) {
        float ra[8];
        *(float4*)&ra[0] = *(const float4*)&As[buf][kk][ty*8];
        *(float4*)&ra[4] = *(const float4*)&As[buf][kk][ty*8+4];
        ulonglong2 rb = *(const ulonglong2*)&Bs[buf][kk][tx*4];
#pragma unroll
        for (int i = 0; i < 8; i++) {
            u64 aa = pack2(ra[i]);
            fma2(acc[i][0], aa, rb.x);
            fma2(acc[i][1], aa, rb.y);
        }
    }

#pragma unroll
    for (int i = 0; i < 8; i++) {
        ulonglong2 v; v.x = acc[i][0]; v.y = acc[i][1];
        *(ulonglong2*)&Om[(size_t)(m0 + ty*8 + i) * H2D + tx*4] = v;
    }
}

// ---------------- conv2 gather ----------------
__global__ void k_gather2(const float* __restrict__ b2, float* __restrict__ out_x1) {
    int t = threadIdx.x;            // 256
    int i = blockIdx.x * 16 + (t >> 4);
    int l = (t & 15) * 4;
    float s2 = g_dinv[i] * g_dinv[i];
    float4 x0 = *(const float4*)&g_XW2 [(size_t)i * H2D + l];
    float4 xc = *(const float4*)&g_XW2c[(size_t)i * H2D + l];
    float4 acc  = make_float4(s2*x0.x, s2*x0.y, s2*x0.z, s2*x0.w);
    float4 accc = make_float4(s2*xc.x, s2*xc.y, s2*xc.z, s2*xc.w);
    int e1 = g_off[i + 1];
    for (int e = g_off[i]; e < e1; e++) {
        int s = g_csr_src[e];
        float nm = g_csr_nm[e];
        float4 xs = *(const float4*)&g_XW2 [(size_t)s * H2D + l];
        float4 xq = *(const float4*)&g_XW2c[(size_t)s * H2D + l];
        acc.x  += nm*xs.x; acc.y  += nm*xs.y; acc.z  += nm*xs.z; acc.w  += nm*xs.w;
        accc.x += nm*xq.x; accc.y += nm*xq.y; accc.z += nm*xq.z; accc.w += nm*xq.w;
    }
    float4 bb = *(const float4*)&b2[l];
    float4 v;
    v.x = fmaxf(acc.x + bb.x, 0.f); v.y = fmaxf(acc.y + bb.y, 0.f);
    v.z = fmaxf(acc.z + bb.z, 0.f); v.w = fmaxf(acc.w + bb.w, 0.f);
    *(float4*)&out_x1[(size_t)i * H2D + l] = v;
    v.x = fmaxf(accc.x + bb.x, 0.f); v.y = fmaxf(accc.y + bb.y, 0.f);
    v.z = fmaxf(accc.z + bb.z, 0.f); v.w = fmaxf(accc.w + bb.w, 0.f);
    *(float4*)&g_X2c[(size_t)i * H2D + l] = v;
}

// ---------------- readout2 (+ bilinear) ----------------
__global__ void k_readout2(const float* __restrict__ Wd, const float* __restrict__ bd,
                           const float* __restrict__ x1,
                           float* __restrict__ ret1, float* __restrict__ ret1c) {
    __shared__ float part1[4][H2D], part2[4][H2D];
    __shared__ float c1[H2D], c2[H2D], h[H2D], hc[H2D];
    __shared__ float red[4][H2D];
    __shared__ float nrm1, nrm2;
    int i = blockIdx.x;
    int tid = threadIdx.x;  // 256
    int cnt = g_mcnt[i];
    float inv = 1.0f / g_mrs[i];

    int g = tid >> 6, f = tid & 63;
    float a1 = 0.f, a2 = 0.f;
    for (int e = g; e < cnt; e += 4) {
        int j = g_midx[i*MCAP + e];
        float mv = g_mval[i*MCAP + e];
        a1 += mv * x1   [(size_t)j * H2D + f];
        a2 += mv * g_X2c[(size_t)j * H2D + f];
    }
    part1[g][f] = a1;
    part2[g][f] = a2;
    __syncthreads();

    if (tid < H2D) {
        c1[tid] = (part1[0][tid] + part1[1][tid] + part1[2][tid] + part1[3][tid]) * inv;
        c2[tid] = (part2[0][tid] + part2[1][tid] + part2[2][tid] + part2[3][tid]) * inv;
        h [tid] = x1   [(size_t)i*H2D + tid];
        hc[tid] = g_X2c[(size_t)i*H2D + tid];
    }
    __syncthreads();
    if (tid == 0) {
        float s1 = 0.f, s2 = 0.f;
        for (int q = 0; q < H2D; q++) { s1 += c1[q]*c1[q]; s2 += c2[q]*c2[q]; }
        nrm1 = fmaxf(sqrtf(s1), 1e-12f);
        nrm2 = fmaxf(sqrtf(s2), 1e-12f);
    }
    __syncthreads();
    if (tid < H2D) {
        c1[tid] = 1.0f / (1.0f + expf(-c1[tid] / nrm1));
        c2[tid] = 1.0f / (1.0f + expf(-c2[tid] / nrm2));
    }
    __syncthreads();
    if (tid < H2D) {
        int k = tid;
        float t1 = 0.f, t2 = 0.f;
        const float4* wr = (const float4*)&Wd[k * H2D];
#pragma unroll
        for (int j4 = 0; j4 < H2D / 4; j4++) {
            float4 w = wr[j4];
            t1 += w.x*c1[j4*4] + w.y*c1[j4*4+1] + w.z*c1[j4*4+2] + w.w*c1[j4*4+3];
            t2 += w.x*c2[j4*4] + w.y*c2[j4*4+1] + w.z*c2[j4*4+2] + w.w*c2[j4*4+3];
        }
        red[0][k] = h [k] * t1;
        red[1][k] = hc[k] * t1;
        red[2][k] = hc[k] * t2;
        red[3][k] = h [k] * t2;
    }
    __syncthreads();
    if (tid < 4) {
        float s = 0.f;
        for (int j = 0; j < H2D; j++) s += red[tid][j];
        s += bd[0];
        if (tid == 0) ret1 [i*2 + 0] = s;
        if (tid == 1) ret1 [i*2 + 1] = s;
        if (tid == 2) ret1c[i*2 + 0] = s;
        if (tid == 3) ret1c[i*2 + 1] = s;
    }
}

// ---------------- launch ----------------
extern "C" void kernel_launch(void* const* d_in, const int* in_sizes, int n_in,
                              void* d_out, int out_size) {
    const float* gene = (const float*)d_in[0];
    const float* mask = (const float*)d_in[1];
    const float* W1   = (const float*)d_in[2];
    const float* b1   = (const float*)d_in[3];
    const float* W2   = (const float*)d_in[4];
    const float* b2   = (const float*)d_in[5];
    const float* Wd   = (const float*)d_in[6];
    const float* bd   = (const float*)d_in[7];
    const void*  edges = d_in[8];
    const void*  perm  = d_in[9];

    float* out    = (float*)d_out;
    float* out_x1 = out;
    float* out_r1 = out + NN * H2D;
    float* out_rc = out + NN * H2D + NN * 2;

    static cudaStream_t s1 = 0, s2 = 0;
    static cudaEvent_t evRoot = 0, evS1 = 0, evS2 = 0;
    static int inited = 0;
    if (!inited) {
        cudaStreamCreateWithFlags(&s1, cudaStreamNonBlocking);
        cudaStreamCreateWithFlags(&s2, cudaStreamNonBlocking);
        cudaEventCreateWithFlags(&evRoot, cudaEventDisableTiming);
        cudaEventCreateWithFlags(&evS1,   cudaEventDisableTiming);
        cudaEventCreateWithFlags(&evS2,   cudaEventDisableTiming);
        cudaFuncSetAttribute(k_gemm1_tc,
                             cudaFuncAttributeMaxDynamicSharedMemorySize, NSTG * STAGEB);
        inited = 1;
    }

    cudaEventRecord(evRoot, 0);
    cudaStreamWaitEvent(s1, evRoot, 0);
    cudaStreamWaitEvent(s2, evRoot, 0);

    k_maskscan <<<NN, 256, 0, s1>>>(mask);                 // #1
    k_convB    <<<H1D * (KPAD/8) / 256, 256>>>(W1);        // #2
    k_init0det <<<EE / 256, 256, 0, s2>>>(edges);          // #3

    dim3 gg1(H1D / 128, NN / 128);                         // (2, 64) = 128 CTAs
    k_gemm1_tc <<<gg1, 256, NSTG * STAGEB>>>(gene);        // #4 (profiled)

    k_perm_int <<<NN / 256, 256, 0, s2>>>(perm);
    k_deg_count<<<EE / 256, 256, 0, s2>>>(edges);
    k_dinv     <<<NN / 256, 256, 0, s2>>>();
    k_scan     <<<1, 256, 0, s2>>>();
    k_fill     <<<EE / 256, 256, 0, s2>>>(edges);

    cudaEventRecord(evS1, s1);
    cudaEventRecord(evS2, s2);
    cudaStreamWaitEvent(0, evS1, 0);
    cudaStreamWaitEvent(0, evS2, 0);

    k_gather1  <<<NN / 2, 128>>>(b1);
    k_gemm2    <<<128, 256>>>(W2);
    k_gather2  <<<NN / 16, 256>>>(b2, out_x1);
    k_readout2 <<<NN, 256>>>(Wd, bd, out_x1, out_r1, out_rc);
}